// round 7
// baseline (speedup 1.0000x reference)
#include <cuda_runtime.h>
#include <cuda_bf16.h>
#include <math.h>
#include <stdint.h>

#define B_ 64
#define S_ 512
#define D_ 512
#define H_ 1024
#define KTOT 1536
#define NBLK 48            // k blocks of 32
#define NBX  16            // blocks covering x (512/32)
#define NCTA 128           // persistent CTAs (<=148 SMs, 1/SM -> barrier safe)
#define WSTR 3088          // weight smem row stride bytes (1536*2 + 16)
#define GSTR 33            // gate smem row stride floats

// smem map
#define SM_WSZ 98816                       // one weight half: 32 rows * 3088
#define SM_A_BASE 197632                   // after both halves
#define SM_AB(buf,half) (SM_A_BASE + (((buf)*2+(half))*5120))   // 64 rows * 80 B
#define SM_G SM_A_BASE                     // gates reuse A buffers (8448 B <= 20480)
#define SMEM_TOTAL 218112

// ---------------- device scratch (allocation-free rule) -------------------
__device__ __nv_bfloat16 g_xhi[(size_t)S_ * B_ * D_];   // [s][b][d]
__device__ __nv_bfloat16 g_xlo[(size_t)S_ * B_ * D_];
__device__ __nv_bfloat16 g_Bhi[(size_t)4096 * KTOT];    // [n=h*4+g][k]  (Wx | Wh)
__device__ __nv_bfloat16 g_Blo[(size_t)4096 * KTOT];
__device__ __nv_bfloat16 g_Hhi[2][B_ * H_];
__device__ __nv_bfloat16 g_Hlo[2][B_ * H_];
__device__ float g_C[B_ * H_];
__device__ float g_outs[(size_t)S_ * B_ * H_];          // [s][b][h]
__device__ unsigned g_bar;

// ---------------- helpers ---------------------------------------------------
__device__ __forceinline__ uint32_t smem_u32(const void* p) {
    uint32_t a;
    asm("{ .reg .u64 t; cvta.to.shared.u64 t, %1; cvt.u32.u64 %0, t; }" : "=r"(a) : "l"(p));
    return a;
}
__device__ __forceinline__ void ldm4(uint32_t* r, uint32_t addr) {
    asm volatile("ldmatrix.sync.aligned.m8n8.x4.shared.b16 {%0,%1,%2,%3}, [%4];"
                 : "=r"(r[0]), "=r"(r[1]), "=r"(r[2]), "=r"(r[3]) : "r"(addr));
}
__device__ __forceinline__ void mma16816(float* d, const uint32_t* a, uint32_t b0, uint32_t b1) {
    asm volatile(
        "mma.sync.aligned.m16n8k16.row.col.f32.bf16.bf16.f32 "
        "{%0,%1,%2,%3}, {%4,%5,%6,%7}, {%8,%9}, {%0,%1,%2,%3};"
        : "+f"(d[0]), "+f"(d[1]), "+f"(d[2]), "+f"(d[3])
        : "r"(a[0]), "r"(a[1]), "r"(a[2]), "r"(a[3]), "r"(b0), "r"(b1));
}
__device__ __forceinline__ float sigmoidf_(float x) { return 1.0f / (1.0f + expf(-x)); }
__device__ __forceinline__ void split_bf16(float v, __nv_bfloat16& hi, __nv_bfloat16& lo) {
    hi = __float2bfloat16_rn(v);
    lo = __float2bfloat16_rn(v - __bfloat162float(hi));
}

// ---------------- conversion / init kernels --------------------------------
__global__ void conv_x(const float* __restrict__ x) {
    size_t n = (size_t)S_ * B_ * D_;
    for (size_t i = blockIdx.x * (size_t)blockDim.x + threadIdx.x; i < n;
         i += (size_t)gridDim.x * blockDim.x) {
        size_t s = i / (B_ * D_);
        size_t r = i % (B_ * D_);
        size_t b = r / D_, d = r % D_;
        split_bf16(x[(b * S_ + s) * D_ + d], g_xhi[i], g_xlo[i]);
    }
}

__global__ void conv_W(const float* __restrict__ Wxi, const float* __restrict__ Wxf,
                       const float* __restrict__ Wxo, const float* __restrict__ Wxc,
                       const float* __restrict__ Whi, const float* __restrict__ Whf,
                       const float* __restrict__ Who, const float* __restrict__ Whc) {
    size_t n = (size_t)4096 * KTOT;
    for (size_t i = blockIdx.x * (size_t)blockDim.x + threadIdx.x; i < n;
         i += (size_t)gridDim.x * blockDim.x) {
        size_t nn = i / KTOT, k = i % KTOT;
        int h = (int)(nn >> 2), g = (int)(nn & 3);
        const float* W;
        size_t off;
        if (k < D_) {
            W = (g == 0) ? Wxi : (g == 1) ? Wxf : (g == 2) ? Wxo : Wxc;
            off = k * H_ + h;
        } else {
            W = (g == 0) ? Whi : (g == 1) ? Whf : (g == 2) ? Who : Whc;
            off = (k - D_) * H_ + h;
        }
        split_bf16(W[off], g_Bhi[i], g_Blo[i]);
    }
}

__global__ void lstm_init(const float* __restrict__ H0, const float* __restrict__ C0) {
    int i = blockIdx.x * blockDim.x + threadIdx.x;
    if (i == 0) g_bar = 0u;
    if (i < B_ * H_) {
        split_bf16(H0[i], g_Hhi[0][i], g_Hlo[0][i]);
        g_C[i] = C0[i];
    }
}

// ---------------- persistent LSTM (weights resident in smem) ---------------
__global__ void __launch_bounds__(256, 1) lstm_persist(
    const float* __restrict__ bi, const float* __restrict__ bf,
    const float* __restrict__ bo, const float* __restrict__ bc)
{
    extern __shared__ __align__(128) char smem[];
    const uint32_t sb = smem_u32(smem);
    const int t    = threadIdx.x;
    const int w    = t >> 5;
    const int lane = t & 31;
    const int n0   = blockIdx.x * 32;

    const int m0    = (w & 3) * 16;
    const int nloc0 = (w >> 2) * 16;
    const int frow  = (lane & 7) + ((lane & 8) ? 8 : 0);
    const int fk    = (lane & 16) ? 16 : 0;
    const uint32_t aoff = (uint32_t)((m0 + frow) * 80 + fk);
    const uint32_t woff = (uint32_t)((nloc0 + frow) * WSTR + fk);

    // ---- load resident weights: 32 rows x 1536 k, hi + lo ----
    for (int idx = t; idx < 32 * 192; idx += 256) {
        int row = idx / 192, c16 = idx % 192;
        size_t goff = (size_t)(n0 + row) * KTOT + c16 * 8;
        *(uint4*)(smem + row * WSTR + c16 * 16)           = *(const uint4*)(g_Bhi + goff);
        *(uint4*)(smem + SM_WSZ + row * WSTR + c16 * 16)  = *(const uint4*)(g_Blo + goff);
    }

    // per-thread epilogue constants
    const int hloc  = t & 7;
    const int hglob = blockIdx.x * 8 + hloc;
    const float bvi = bi[hglob], bvf = bf[hglob], bvo = bo[hglob], bvc = bc[hglob];

    const int arow = t >> 2, ac16 = t & 3;
    __syncthreads();

    for (int s = 0; s < S_; s++) {
        const int cur = s & 1;
        const __nv_bfloat16* Hh = g_Hhi[cur];
        const __nv_bfloat16* Hl = g_Hlo[cur];
        const size_t xo = (size_t)s * B_ * D_;

        uint4 pah, pal;
        auto prefetch = [&](int c) {
            if (c < NBX) {
                size_t o = xo + (size_t)arow * D_ + c * 32 + ac16 * 8;
                pah = *(const uint4*)(g_xhi + o);
                pal = *(const uint4*)(g_xlo + o);
            } else {
                size_t o = (size_t)arow * H_ + (c - NBX) * 32 + ac16 * 8;
                pah = __ldcg((const uint4*)(Hh + o));   // bypass L1: stale-line hazard
                pal = __ldcg((const uint4*)(Hl + o));
            }
        };
        auto store_buf = [&](int buf) {
            const int o = arow * 80 + ac16 * 16;
            *(uint4*)(smem + SM_AB(buf, 0) + o) = pah;
            *(uint4*)(smem + SM_AB(buf, 1) + o) = pal;
        };

        float ahh[8], amx[8];
#pragma unroll
        for (int i = 0; i < 8; i++) { ahh[i] = 0.f; amx[i] = 0.f; }

        prefetch(0); store_buf(0); __syncthreads();
        prefetch(1);

        for (int c = 0; c < NBLK; c++) {
            const int buf = c & 1;
            const uint32_t a_h = sb + SM_AB(buf, 0) + aoff;
            const uint32_t a_l = sb + SM_AB(buf, 1) + aoff;
            const uint32_t b_h = sb + woff + c * 64;
            const uint32_t b_l = sb + SM_WSZ + woff + c * 64;
#pragma unroll
            for (int ks = 0; ks < 2; ks++) {
                uint32_t fa_h[4], fa_l[4], fb_h[4], fb_l[4];
                ldm4(fa_h, a_h + ks * 32);
                ldm4(fb_h, b_h + ks * 32);
                ldm4(fa_l, a_l + ks * 32);
                ldm4(fb_l, b_l + ks * 32);
                mma16816(ahh,     fa_h, fb_h[0], fb_h[2]);
                mma16816(ahh + 4, fa_h, fb_h[1], fb_h[3]);
                mma16816(amx,     fa_h, fb_l[0], fb_l[2]);
                mma16816(amx + 4, fa_h, fb_l[1], fb_l[3]);
                mma16816(amx,     fa_l, fb_h[0], fb_h[2]);
                mma16816(amx + 4, fa_l, fb_h[1], fb_h[3]);
            }
            if (c + 1 < NBLK) {
                store_buf(buf ^ 1);
                __syncthreads();
                if (c + 2 < NBLK) prefetch(c + 2);
            }
        }

        // ---- epilogue ----
        __syncthreads();                          // done reading A bufs (gates overlap)
        float* sg = (float*)(smem + SM_G);
        {
            const int r0 = m0 + (lane >> 2);
            const int c0 = nloc0 + 2 * (lane & 3);
            sg[r0 * GSTR + c0]           = ahh[0] + amx[0];
            sg[r0 * GSTR + c0 + 1]       = ahh[1] + amx[1];
            sg[(r0 + 8) * GSTR + c0]     = ahh[2] + amx[2];
            sg[(r0 + 8) * GSTR + c0 + 1] = ahh[3] + amx[3];
            sg[r0 * GSTR + c0 + 8]       = ahh[4] + amx[4];
            sg[r0 * GSTR + c0 + 9]       = ahh[5] + amx[5];
            sg[(r0 + 8) * GSTR + c0 + 8] = ahh[6] + amx[6];
            sg[(r0 + 8) * GSTR + c0 + 9] = ahh[7] + amx[7];
        }
        __syncthreads();

        __nv_bfloat16* Hnh = g_Hhi[cur ^ 1];
        __nv_bfloat16* Hnl = g_Hlo[cur ^ 1];
#pragma unroll
        for (int j = 0; j < 2; j++) {
            const int idx = t + j * 256;
            const int b   = idx >> 3;
            const float* gr = sg + b * GSTR + hloc * 4;
            float iv = sigmoidf_(gr[0] + bvi);
            float fv = sigmoidf_(gr[1] + bvf);
            float ov = sigmoidf_(gr[2] + bvo);
            float cv = tanhf(gr[3] + bvc);
            float cn = fv * g_C[b * H_ + hglob] + iv * cv;
            float hn = ov * tanhf(cn);
            g_C[b * H_ + hglob] = cn;
            g_outs[((size_t)s * B_ + b) * H_ + hglob] = hn;
            __nv_bfloat16 hh, hl;
            split_bf16(hn, hh, hl);
            Hnh[b * H_ + hglob] = hh;
            Hnl[b * H_ + hglob] = hl;
        }

        // ---- grid barrier (all 128 CTAs resident: safe) ----
        __syncthreads();
        if (t == 0) {
            __threadfence();                       // release
            atomicAdd(&g_bar, 1u);
            const unsigned tgt = (unsigned)NCTA * (unsigned)(s + 1);
            while (*(volatile unsigned*)&g_bar < tgt) { }
            __threadfence();                       // acquire
        }
        __syncthreads();
    }
}

// ---------------- fc + finalize --------------------------------------------
__global__ void fc_kernel(const float* __restrict__ fcW,
                          const float* __restrict__ fcb,
                          float* __restrict__ pred)
{
    int gw = (blockIdx.x * blockDim.x + threadIdx.x) >> 5;
    int lane = threadIdx.x & 31;
    if (gw >= B_ * S_) return;
    int s = gw >> 6;
    int b = gw & 63;
    const float* row = g_outs + ((size_t)s * B_ + b) * H_;
    float sum = 0.0f;
#pragma unroll 4
    for (int h = lane; h < H_; h += 32) sum += row[h] * fcW[h];
#pragma unroll
    for (int o = 16; o; o >>= 1) sum += __shfl_down_sync(0xFFFFFFFFu, sum, o);
    if (lane == 0) pred[(size_t)b * S_ + s] = sum + fcb[0];
}

__global__ void finalize_kernel(float* __restrict__ out, int out_size) {
    int i = blockIdx.x * blockDim.x + threadIdx.x;
    if (i >= B_ * H_) return;
    const int PRED = B_ * S_;
    if (out_size >= PRED + B_ * H_)
        out[PRED + i] = g_outs[((size_t)(S_ - 1) * B_) * H_ + i];
    if (out_size >= PRED + 2 * B_ * H_)
        out[PRED + B_ * H_ + i] = g_C[i];
}

// ---------------------------------------------------------------------------
extern "C" void kernel_launch(void* const* d_in, const int* in_sizes, int n_in,
                              void* d_out, int out_size)
{
    const float* inputs = (const float*)d_in[0];
    const float* H0  = (const float*)d_in[1];
    const float* C0  = (const float*)d_in[2];
    const float* Wxi = (const float*)d_in[3];
    const float* Whi = (const float*)d_in[4];
    const float* bi  = (const float*)d_in[5];
    const float* Wxf = (const float*)d_in[6];
    const float* Whf = (const float*)d_in[7];
    const float* bf  = (const float*)d_in[8];
    const float* Wxo = (const float*)d_in[9];
    const float* Who = (const float*)d_in[10];
    const float* bo  = (const float*)d_in[11];
    const float* Wxc = (const float*)d_in[12];
    const float* Whc = (const float*)d_in[13];
    const float* bc  = (const float*)d_in[14];
    const float* fcW = (const float*)d_in[15];
    const float* fcb = (const float*)d_in[16];
    float* out = (float*)d_out;

    cudaFuncSetAttribute(lstm_persist, cudaFuncAttributeMaxDynamicSharedMemorySize, SMEM_TOTAL);

    conv_x<<<4096, 256>>>(inputs);
    conv_W<<<3072, 256>>>(Wxi, Wxf, Wxo, Wxc, Whi, Whf, Who, Whc);
    lstm_init<<<(B_ * H_ + 255) / 256, 256>>>(H0, C0);

    lstm_persist<<<NCTA, 256, SMEM_TOTAL>>>(bi, bf, bo, bc);

    fc_kernel<<<(B_ * S_) / 8, 256>>>(fcW, fcb, out);
    finalize_kernel<<<(B_ * H_ + 255) / 256, 256>>>(out, out_size);
}

// round 8
// speedup vs baseline: 1.6021x; 1.6021x over previous
#include <cuda_runtime.h>
#include <cuda_bf16.h>
#include <math.h>
#include <stdint.h>

#define B_ 64
#define S_ 512
#define D_ 512
#define H_ 1024
#define KTOT 1536
#define NCTA 128           // persistent CTAs (<=148 SMs, 1/SM -> barrier safe)
#define GSTR 33            // gate smem row stride floats

// ---- persistent kernel smem map ----
#define PW_STR   2064      // weight row stride bytes (1024*2 + 16)
#define PSM_WLO  66048     // lo weights after hi (32*2064)
#define PSM_RING 132096    // 4-stage A ring
#define PSM_STG  18432     // per stage: hi 9216 (64*144) + lo 9216
#define PSM_G    205824    // gates 64*33*4 = 8448
#define PSM_TOTAL 214272

// ---- xproj kernel smem map ----
#define XP_SM_A(buf,half) (((buf)*2+(half))*10240)          // 128 rows * 80 B
#define XP_SM_B(buf,half) (40960 + ((buf)*2+(half))*5120)   // 64 rows * 80 B
#define XP_SMEM 61440

// ---------------- device scratch (allocation-free rule) -------------------
__device__ __nv_bfloat16 g_xhi[(size_t)S_ * B_ * D_];   // [s][b][d]
__device__ __nv_bfloat16 g_xlo[(size_t)S_ * B_ * D_];
__device__ __nv_bfloat16 g_Bhi[(size_t)4096 * KTOT];    // [n=h*4+g][k]  (Wx | Wh)
__device__ __nv_bfloat16 g_Blo[(size_t)4096 * KTOT];
__device__ float g_xp[(size_t)S_ * B_ * 4096];          // precomputed x@Wx
__device__ __nv_bfloat16 g_Hhi[2][B_ * H_];
__device__ __nv_bfloat16 g_Hlo[2][B_ * H_];
__device__ float g_C[B_ * H_];
__device__ float g_outs[(size_t)S_ * B_ * H_];          // [s][b][h]
__device__ unsigned g_bar;

// ---------------- helpers ---------------------------------------------------
__device__ __forceinline__ uint32_t smem_u32(const void* p) {
    uint32_t a;
    asm("{ .reg .u64 t; cvta.to.shared.u64 t, %1; cvt.u32.u64 %0, t; }" : "=r"(a) : "l"(p));
    return a;
}
__device__ __forceinline__ void ldm4(uint32_t* r, uint32_t addr) {
    asm volatile("ldmatrix.sync.aligned.m8n8.x4.shared.b16 {%0,%1,%2,%3}, [%4];"
                 : "=r"(r[0]), "=r"(r[1]), "=r"(r[2]), "=r"(r[3]) : "r"(addr));
}
__device__ __forceinline__ void mma16816(float* d, const uint32_t* a, uint32_t b0, uint32_t b1) {
    asm volatile(
        "mma.sync.aligned.m16n8k16.row.col.f32.bf16.bf16.f32 "
        "{%0,%1,%2,%3}, {%4,%5,%6,%7}, {%8,%9}, {%0,%1,%2,%3};"
        : "+f"(d[0]), "+f"(d[1]), "+f"(d[2]), "+f"(d[3])
        : "r"(a[0]), "r"(a[1]), "r"(a[2]), "r"(a[3]), "r"(b0), "r"(b1));
}
__device__ __forceinline__ void cp16(uint32_t s, const void* g) {
    asm volatile("cp.async.cg.shared.global [%0], [%1], 16;" :: "r"(s), "l"(g));
}
__device__ __forceinline__ float sigmoidf_(float x) { return 1.0f / (1.0f + expf(-x)); }
__device__ __forceinline__ void split_bf16(float v, __nv_bfloat16& hi, __nv_bfloat16& lo) {
    hi = __float2bfloat16_rn(v);
    lo = __float2bfloat16_rn(v - __bfloat162float(hi));
}

// ---------------- conversion / init kernels --------------------------------
__global__ void conv_x(const float* __restrict__ x) {
    size_t n = (size_t)S_ * B_ * D_;
    for (size_t i = blockIdx.x * (size_t)blockDim.x + threadIdx.x; i < n;
         i += (size_t)gridDim.x * blockDim.x) {
        size_t s = i / (B_ * D_);
        size_t r = i % (B_ * D_);
        size_t b = r / D_, d = r % D_;
        split_bf16(x[(b * S_ + s) * D_ + d], g_xhi[i], g_xlo[i]);
    }
}

__global__ void conv_W(const float* __restrict__ Wxi, const float* __restrict__ Wxf,
                       const float* __restrict__ Wxo, const float* __restrict__ Wxc,
                       const float* __restrict__ Whi, const float* __restrict__ Whf,
                       const float* __restrict__ Who, const float* __restrict__ Whc) {
    size_t n = (size_t)4096 * KTOT;
    for (size_t i = blockIdx.x * (size_t)blockDim.x + threadIdx.x; i < n;
         i += (size_t)gridDim.x * blockDim.x) {
        size_t nn = i / KTOT, k = i % KTOT;
        int h = (int)(nn >> 2), g = (int)(nn & 3);
        const float* W;
        size_t off;
        if (k < D_) {
            W = (g == 0) ? Wxi : (g == 1) ? Wxf : (g == 2) ? Wxo : Wxc;
            off = k * H_ + h;
        } else {
            W = (g == 0) ? Whi : (g == 1) ? Whf : (g == 2) ? Who : Whc;
            off = (k - D_) * H_ + h;
        }
        split_bf16(W[off], g_Bhi[i], g_Blo[i]);
    }
}

__global__ void lstm_init(const float* __restrict__ H0, const float* __restrict__ C0) {
    int i = blockIdx.x * blockDim.x + threadIdx.x;
    if (i == 0) g_bar = 0u;
    if (i < B_ * H_) {
        split_bf16(H0[i], g_Hhi[0][i], g_Hlo[0][i]);
        g_C[i] = C0[i];
    }
}

// ---------------- xproj: xp[M=32768][4096] = x @ Wx (split-bf16 x3) --------
__global__ void __launch_bounds__(256, 1) xproj_gemm() {
    extern __shared__ __align__(128) char smem[];
    const uint32_t sb = smem_u32(smem);
    const int t = threadIdx.x, w = t >> 5, lane = t & 31;
    const int m0g = blockIdx.y * 128;
    const int n0g = blockIdx.x * 64;
    const int mw = (w & 3) * 32, nw = (w >> 2) * 32;
    const int frow = (lane & 7) + ((lane & 8) ? 8 : 0);
    const int fk   = (lane & 16) ? 16 : 0;

    const int brow = t >> 2, bc16 = t & 3;

    uint4 pah[2], pal[2], pbh, pbl;
    auto prefetch = [&](int kb) {
#pragma unroll
        for (int i = 0; i < 2; i++) {
            int idx = t + i * 256, row = idx >> 2, c16 = idx & 3;
            size_t o = (size_t)(m0g + row) * D_ + kb * 32 + c16 * 8;
            pah[i] = *(const uint4*)(g_xhi + o);
            pal[i] = *(const uint4*)(g_xlo + o);
        }
        size_t ob = (size_t)(n0g + brow) * KTOT + kb * 32 + bc16 * 8;
        pbh = *(const uint4*)(g_Bhi + ob);
        pbl = *(const uint4*)(g_Blo + ob);
    };
    auto store_buf = [&](int buf) {
#pragma unroll
        for (int i = 0; i < 2; i++) {
            int idx = t + i * 256, row = idx >> 2, c16 = idx & 3;
            *(uint4*)(smem + XP_SM_A(buf, 0) + row * 80 + c16 * 16) = pah[i];
            *(uint4*)(smem + XP_SM_A(buf, 1) + row * 80 + c16 * 16) = pal[i];
        }
        *(uint4*)(smem + XP_SM_B(buf, 0) + brow * 80 + bc16 * 16) = pbh;
        *(uint4*)(smem + XP_SM_B(buf, 1) + brow * 80 + bc16 * 16) = pbl;
    };

    float ahh[32], amx[32];
#pragma unroll
    for (int i = 0; i < 32; i++) { ahh[i] = 0.f; amx[i] = 0.f; }

    prefetch(0); store_buf(0); __syncthreads();

    for (int kb = 0; kb < 16; kb++) {
        const int buf = kb & 1;
        if (kb + 1 < 16) prefetch(kb + 1);
        const uint32_t aH = sb + XP_SM_A(buf, 0), aL = sb + XP_SM_A(buf, 1);
        const uint32_t bH = sb + XP_SM_B(buf, 0), bL = sb + XP_SM_B(buf, 1);
#pragma unroll
        for (int ks = 0; ks < 2; ks++) {
            uint32_t fah[2][4], fal[2][4], fbh[2][4], fbl[2][4];
#pragma unroll
            for (int mi = 0; mi < 2; mi++) {
                ldm4(fah[mi], aH + (mw + mi * 16 + frow) * 80 + fk + ks * 32);
                ldm4(fal[mi], aL + (mw + mi * 16 + frow) * 80 + fk + ks * 32);
            }
#pragma unroll
            for (int ni = 0; ni < 2; ni++) {
                ldm4(fbh[ni], bH + (nw + ni * 16 + frow) * 80 + fk + ks * 32);
                ldm4(fbl[ni], bL + (nw + ni * 16 + frow) * 80 + fk + ks * 32);
            }
#pragma unroll
            for (int mi = 0; mi < 2; mi++)
#pragma unroll
                for (int ni = 0; ni < 2; ni++) {
                    float* ph = &ahh[(mi * 2 + ni) * 8];
                    float* pm = &amx[(mi * 2 + ni) * 8];
                    mma16816(ph,     fah[mi], fbh[ni][0], fbh[ni][2]);
                    mma16816(ph + 4, fah[mi], fbh[ni][1], fbh[ni][3]);
                    mma16816(pm,     fah[mi], fbl[ni][0], fbl[ni][2]);
                    mma16816(pm + 4, fah[mi], fbl[ni][1], fbl[ni][3]);
                    mma16816(pm,     fal[mi], fbh[ni][0], fbh[ni][2]);
                    mma16816(pm + 4, fal[mi], fbh[ni][1], fbh[ni][3]);
                }
        }
        if (kb + 1 < 16) { __syncthreads(); store_buf(buf ^ 1); __syncthreads(); }
    }

    // epilogue: write fp32 xp
#pragma unroll
    for (int mi = 0; mi < 2; mi++)
#pragma unroll
        for (int ni = 0; ni < 2; ni++)
#pragma unroll
            for (int u = 0; u < 2; u++) {
                const float* ph = &ahh[(mi * 2 + ni) * 8 + u * 4];
                const float* pm = &amx[(mi * 2 + ni) * 8 + u * 4];
                size_t r0 = (size_t)(m0g + mw + mi * 16 + (lane >> 2));
                int    c0 = n0g + nw + ni * 16 + u * 8 + 2 * (lane & 3);
                float2 v0 = make_float2(ph[0] + pm[0], ph[1] + pm[1]);
                float2 v1 = make_float2(ph[2] + pm[2], ph[3] + pm[3]);
                *(float2*)(g_xp + r0 * 4096 + c0)       = v0;
                *(float2*)(g_xp + (r0 + 8) * 4096 + c0) = v1;
            }
}

// ---------------- persistent recurrence (K=1024, weights resident) ---------
__global__ void __launch_bounds__(256, 1) lstm_persist(
    const float* __restrict__ bi, const float* __restrict__ bf,
    const float* __restrict__ bo, const float* __restrict__ bc)
{
    extern __shared__ __align__(128) char smem[];
    const uint32_t sb = smem_u32(smem);
    const int t    = threadIdx.x;
    const int w    = t >> 5;
    const int lane = t & 31;
    const int n0   = blockIdx.x * 32;

    const int m0    = (w & 3) * 16;
    const int nloc0 = (w >> 2) * 16;
    const int frow  = (lane & 7) + ((lane & 8) ? 8 : 0);
    const int fk    = (lane & 16) ? 16 : 0;
    const uint32_t aoff = (uint32_t)((m0 + frow) * 144 + fk);
    const uint32_t woff = (uint32_t)((nloc0 + frow) * PW_STR + fk);

    // ---- resident weights: Wh slice (K=1024 at KTOT offset 512), hi+lo ----
#pragma unroll
    for (int i = 0; i < 16; i++) {
        int idx = t + i * 256;             // 0..4095 chunks of 16B
        int row = idx >> 7, c16 = idx & 127;
        size_t go = (size_t)(n0 + row) * KTOT + 512 + c16 * 8;
        *(uint4*)(smem + row * PW_STR + c16 * 16)            = *(const uint4*)(g_Bhi + go);
        *(uint4*)(smem + PSM_WLO + row * PW_STR + c16 * 16)  = *(const uint4*)(g_Blo + go);
    }

    const int hloc  = t & 7;
    const int hglob = blockIdx.x * 8 + hloc;
    const float bvi = bi[hglob], bvf = bf[hglob], bvo = bo[hglob], bvc = bc[hglob];
    __syncthreads();

    for (int s = 0; s < S_; s++) {
        const int cur = s & 1;
        const __nv_bfloat16* Hh = g_Hhi[cur];
        const __nv_bfloat16* Hl = g_Hlo[cur];

        // ---- acc init from precomputed x-projection ----
        float ahh[8], amx[8];
        {
            const size_t xr = ((size_t)s * 64 + m0 + (lane >> 2)) * 4096
                              + n0 + nloc0 + 2 * (lane & 3);
            float2 v0 = *(const float2*)(g_xp + xr);
            float2 v1 = *(const float2*)(g_xp + xr + 8);
            float2 v2 = *(const float2*)(g_xp + xr + 8 * 4096);
            float2 v3 = *(const float2*)(g_xp + xr + 8 * 4096 + 8);
            ahh[0] = v0.x; ahh[1] = v0.y; ahh[2] = v2.x; ahh[3] = v2.y;
            ahh[4] = v1.x; ahh[5] = v1.y; ahh[6] = v3.x; ahh[7] = v3.y;
#pragma unroll
            for (int i = 0; i < 8; i++) amx[i] = 0.f;
        }

        // ---- cp.async 4-stage ring over 16 k64 blocks of H ----
        auto issue_stage = [&](int c) {
            const int st = c & 3;
            const uint32_t base = sb + PSM_RING + st * PSM_STG;
#pragma unroll
            for (int i = 0; i < 2; i++) {
                int idx = t + i * 256, row = idx >> 3, c16 = idx & 7;
                int go = row * H_ + c * 64 + c16 * 8;
                uint32_t so = row * 144 + c16 * 16;
                cp16(base + so,        Hh + go);
                cp16(base + 9216 + so, Hl + go);
            }
            asm volatile("cp.async.commit_group;" ::: "memory");
        };

        issue_stage(0); issue_stage(1); issue_stage(2);

        for (int c = 0; c < 16; c++) {
            if (c < 14)       asm volatile("cp.async.wait_group 2;" ::: "memory");
            else if (c == 14) asm volatile("cp.async.wait_group 1;" ::: "memory");
            else              asm volatile("cp.async.wait_group 0;" ::: "memory");
            __syncthreads();
            if (c + 3 < 16) issue_stage(c + 3);

            const int st = c & 3;
            const uint32_t aH = sb + PSM_RING + st * PSM_STG + aoff;
            const uint32_t aL = aH + 9216;
            const uint32_t bH = sb + woff + c * 128;
            const uint32_t bL = bH + PSM_WLO;
#pragma unroll
            for (int ks = 0; ks < 4; ks++) {
                uint32_t fa_h[4], fa_l[4], fb_h[4], fb_l[4];
                ldm4(fa_h, aH + ks * 32);
                ldm4(fb_h, bH + ks * 32);
                ldm4(fa_l, aL + ks * 32);
                ldm4(fb_l, bL + ks * 32);
                mma16816(ahh,     fa_h, fb_h[0], fb_h[2]);
                mma16816(ahh + 4, fa_h, fb_h[1], fb_h[3]);
                mma16816(amx,     fa_h, fb_l[0], fb_l[2]);
                mma16816(amx + 4, fa_h, fb_l[1], fb_l[3]);
                mma16816(amx,     fa_l, fb_h[0], fb_h[2]);
                mma16816(amx + 4, fa_l, fb_h[1], fb_h[3]);
            }
        }

        // ---- epilogue: gates -> smem -> cell update ----
        __syncthreads();
        float* sg = (float*)(smem + PSM_G);
        {
            const int r0 = m0 + (lane >> 2);
            const int c0 = nloc0 + 2 * (lane & 3);
            sg[r0 * GSTR + c0]           = ahh[0] + amx[0];
            sg[r0 * GSTR + c0 + 1]       = ahh[1] + amx[1];
            sg[(r0 + 8) * GSTR + c0]     = ahh[2] + amx[2];
            sg[(r0 + 8) * GSTR + c0 + 1] = ahh[3] + amx[3];
            sg[r0 * GSTR + c0 + 8]       = ahh[4] + amx[4];
            sg[r0 * GSTR + c0 + 9]       = ahh[5] + amx[5];
            sg[(r0 + 8) * GSTR + c0 + 8] = ahh[6] + amx[6];
            sg[(r0 + 8) * GSTR + c0 + 9] = ahh[7] + amx[7];
        }
        __syncthreads();

        __nv_bfloat16* Hnh = g_Hhi[cur ^ 1];
        __nv_bfloat16* Hnl = g_Hlo[cur ^ 1];
#pragma unroll
        for (int j = 0; j < 2; j++) {
            const int idx = t + j * 256;
            const int b   = idx >> 3;
            const float* gr = sg + b * GSTR + hloc * 4;
            float iv = sigmoidf_(gr[0] + bvi);
            float fv = sigmoidf_(gr[1] + bvf);
            float ov = sigmoidf_(gr[2] + bvo);
            float cv = tanhf(gr[3] + bvc);
            float cn = fv * g_C[b * H_ + hglob] + iv * cv;
            float hn = ov * tanhf(cn);
            g_C[b * H_ + hglob] = cn;
            g_outs[((size_t)s * B_ + b) * H_ + hglob] = hn;
            __nv_bfloat16 hh, hl;
            split_bf16(hn, hh, hl);
            Hnh[b * H_ + hglob] = hh;
            Hnl[b * H_ + hglob] = hl;
        }

        // ---- grid barrier (all 128 CTAs resident) ----
        __syncthreads();
        if (t == 0) {
            __threadfence();
            atomicAdd(&g_bar, 1u);
            const unsigned tgt = (unsigned)NCTA * (unsigned)(s + 1);
            while (*(volatile unsigned*)&g_bar < tgt) { }
            __threadfence();
        }
        __syncthreads();
    }
}

// ---------------- fc + finalize --------------------------------------------
__global__ void fc_kernel(const float* __restrict__ fcW,
                          const float* __restrict__ fcb,
                          float* __restrict__ pred)
{
    int gw = (blockIdx.x * blockDim.x + threadIdx.x) >> 5;
    int lane = threadIdx.x & 31;
    if (gw >= B_ * S_) return;
    int s = gw >> 6;
    int b = gw & 63;
    const float* row = g_outs + ((size_t)s * B_ + b) * H_;
    float sum = 0.0f;
#pragma unroll 4
    for (int h = lane; h < H_; h += 32) sum += row[h] * fcW[h];
#pragma unroll
    for (int o = 16; o; o >>= 1) sum += __shfl_down_sync(0xFFFFFFFFu, sum, o);
    if (lane == 0) pred[(size_t)b * S_ + s] = sum + fcb[0];
}

__global__ void finalize_kernel(float* __restrict__ out, int out_size) {
    int i = blockIdx.x * blockDim.x + threadIdx.x;
    if (i >= B_ * H_) return;
    const int PRED = B_ * S_;
    if (out_size >= PRED + B_ * H_)
        out[PRED + i] = g_outs[((size_t)(S_ - 1) * B_) * H_ + i];
    if (out_size >= PRED + 2 * B_ * H_)
        out[PRED + B_ * H_ + i] = g_C[i];
}

// ---------------------------------------------------------------------------
extern "C" void kernel_launch(void* const* d_in, const int* in_sizes, int n_in,
                              void* d_out, int out_size)
{
    const float* inputs = (const float*)d_in[0];
    const float* H0  = (const float*)d_in[1];
    const float* C0  = (const float*)d_in[2];
    const float* Wxi = (const float*)d_in[3];
    const float* Whi = (const float*)d_in[4];
    const float* bi  = (const float*)d_in[5];
    const float* Wxf = (const float*)d_in[6];
    const float* Whf = (const float*)d_in[7];
    const float* bf  = (const float*)d_in[8];
    const float* Wxo = (const float*)d_in[9];
    const float* Who = (const float*)d_in[10];
    const float* bo  = (const float*)d_in[11];
    const float* Wxc = (const float*)d_in[12];
    const float* Whc = (const float*)d_in[13];
    const float* bc  = (const float*)d_in[14];
    const float* fcW = (const float*)d_in[15];
    const float* fcb = (const float*)d_in[16];
    float* out = (float*)d_out;

    cudaFuncSetAttribute(lstm_persist, cudaFuncAttributeMaxDynamicSharedMemorySize, PSM_TOTAL);
    cudaFuncSetAttribute(xproj_gemm,  cudaFuncAttributeMaxDynamicSharedMemorySize, XP_SMEM);

    conv_x<<<4096, 256>>>(inputs);
    conv_W<<<3072, 256>>>(Wxi, Wxf, Wxo, Wxc, Whi, Whf, Who, Whc);
    lstm_init<<<(B_ * H_ + 255) / 256, 256>>>(H0, C0);

    xproj_gemm<<<dim3(64, 256), 256, XP_SMEM>>>();

    lstm_persist<<<NCTA, 256, PSM_TOTAL>>>(bi, bf, bo, bc);

    fc_kernel<<<(B_ * S_) / 8, 256>>>(fcW, fcb, out);
    finalize_kernel<<<(B_ * H_ + 255) / 256, 256>>>(out, out_size);
}

// round 11
// speedup vs baseline: 2.2981x; 1.4344x over previous
#include <cuda_runtime.h>
#include <cuda_bf16.h>
#include <cuda_fp16.h>
#include <math.h>
#include <stdint.h>

#define B_ 64
#define S_ 512
#define D_ 512
#define H_ 1024
#define NCTA 128           // persistent CTAs, 1/SM -> grid barrier safe

// ---- persistent kernel smem map (bytes) ----
#define WS_STR 2064                    // 1024 fp16 + 16B pad
#define SM_A   66048                   // weights: 32*2064
#define SM_G   198144                  // A: 64*2064 = 132096
#define SM_XP  215040                  // gates: 2 copies * 64*33*4 = 16896
#define PSM_TOTAL 223232               // + xp 8192

// ---- xproj kernel smem map ----
#define XP_SM_A(buf,half) (((buf)*2+(half))*10240)          // 128 rows * 80 B
#define XP_SM_B(buf,half) (40960 + ((buf)*2+(half))*5120)   // 64 rows * 80 B
#define XP_SMEM 61440

// ---------------- device scratch (allocation-free rule) -------------------
__device__ __nv_bfloat16 g_xhi[(size_t)S_ * B_ * D_];   // [s][b][d]
__device__ __nv_bfloat16 g_xlo[(size_t)S_ * B_ * D_];
__device__ __nv_bfloat16 g_Bhi[(size_t)4096 * D_];      // Wx [n=h*4+g][k<512]
__device__ __nv_bfloat16 g_Blo[(size_t)4096 * D_];
__device__ __half        g_Wh16[(size_t)4096 * H_];     // Wh fp16 [n][k]
__device__ float g_xp[(size_t)S_ * B_ * 4096];          // x@Wx fp32
__device__ __half g_Hf[2][B_ * H_];                     // H state fp16
__device__ float g_C[B_ * H_];
__device__ float g_outs[(size_t)S_ * B_ * H_];          // [s][b][h]
__device__ unsigned g_bar;

// ---------------- helpers ---------------------------------------------------
__device__ __forceinline__ uint32_t smem_u32(const void* p) {
    uint32_t a;
    asm("{ .reg .u64 t; cvta.to.shared.u64 t, %1; cvt.u32.u64 %0, t; }" : "=r"(a) : "l"(p));
    return a;
}
__device__ __forceinline__ void ldm4(uint32_t* r, uint32_t addr) {
    asm volatile("ldmatrix.sync.aligned.m8n8.x4.shared.b16 {%0,%1,%2,%3}, [%4];"
                 : "=r"(r[0]), "=r"(r[1]), "=r"(r[2]), "=r"(r[3]) : "r"(addr));
}
__device__ __forceinline__ void mma_bf16(float* d, const uint32_t* a, uint32_t b0, uint32_t b1) {
    asm volatile(
        "mma.sync.aligned.m16n8k16.row.col.f32.bf16.bf16.f32 "
        "{%0,%1,%2,%3}, {%4,%5,%6,%7}, {%8,%9}, {%0,%1,%2,%3};"
        : "+f"(d[0]), "+f"(d[1]), "+f"(d[2]), "+f"(d[3])
        : "r"(a[0]), "r"(a[1]), "r"(a[2]), "r"(a[3]), "r"(b0), "r"(b1));
}
__device__ __forceinline__ void mma_f16(float* d, const uint32_t* a, uint32_t b0, uint32_t b1) {
    asm volatile(
        "mma.sync.aligned.m16n8k16.row.col.f32.f16.f16.f32 "
        "{%0,%1,%2,%3}, {%4,%5,%6,%7}, {%8,%9}, {%0,%1,%2,%3};"
        : "+f"(d[0]), "+f"(d[1]), "+f"(d[2]), "+f"(d[3])
        : "r"(a[0]), "r"(a[1]), "r"(a[2]), "r"(a[3]), "r"(b0), "r"(b1));
}
__device__ __forceinline__ void cp16(uint32_t s, const void* g) {
    asm volatile("cp.async.cg.shared.global [%0], [%1], 16;" :: "r"(s), "l"(g));
}
__device__ __forceinline__ float sigmoidf_(float x) { return 1.0f / (1.0f + expf(-x)); }
__device__ __forceinline__ void split_bf16(float v, __nv_bfloat16& hi, __nv_bfloat16& lo) {
    hi = __float2bfloat16_rn(v);
    lo = __float2bfloat16_rn(v - __bfloat162float(hi));
}

// ---------------- conversion / init kernels --------------------------------
__global__ void conv_x(const float* __restrict__ x) {
    size_t n = (size_t)S_ * B_ * D_;
    for (size_t i = blockIdx.x * (size_t)blockDim.x + threadIdx.x; i < n;
         i += (size_t)gridDim.x * blockDim.x) {
        size_t s = i / (B_ * D_);
        size_t r = i % (B_ * D_);
        size_t b = r / D_, d = r % D_;
        split_bf16(x[(b * S_ + s) * D_ + d], g_xhi[i], g_xlo[i]);
    }
}

__global__ void conv_W(const float* __restrict__ Wxi, const float* __restrict__ Wxf,
                       const float* __restrict__ Wxo, const float* __restrict__ Wxc,
                       const float* __restrict__ Whi, const float* __restrict__ Whf,
                       const float* __restrict__ Who, const float* __restrict__ Whc) {
    size_t n = (size_t)4096 * 1536;
    for (size_t i = blockIdx.x * (size_t)blockDim.x + threadIdx.x; i < n;
         i += (size_t)gridDim.x * blockDim.x) {
        size_t nn = i / 1536, k = i % 1536;
        int h = (int)(nn >> 2), g = (int)(nn & 3);
        if (k < D_) {
            const float* W = (g == 0) ? Wxi : (g == 1) ? Wxf : (g == 2) ? Wxo : Wxc;
            split_bf16(W[k * H_ + h], g_Bhi[nn * D_ + k], g_Blo[nn * D_ + k]);
        } else {
            const float* W = (g == 0) ? Whi : (g == 1) ? Whf : (g == 2) ? Who : Whc;
            g_Wh16[nn * H_ + (k - D_)] = __float2half_rn(W[(k - D_) * H_ + h]);
        }
    }
}

__global__ void lstm_init(const float* __restrict__ H0, const float* __restrict__ C0) {
    int i = blockIdx.x * blockDim.x + threadIdx.x;
    if (i == 0) g_bar = 0u;
    if (i < B_ * H_) {
        g_Hf[0][i] = __float2half_rn(H0[i]);
        g_C[i] = C0[i];
    }
}

// ---------------- xproj: xp[32768][4096] = x @ Wx (split-bf16 x3) ----------
__global__ void __launch_bounds__(256, 1) xproj_gemm() {
    extern __shared__ __align__(128) char smem[];
    const uint32_t sb = smem_u32(smem);
    const int t = threadIdx.x, w = t >> 5, lane = t & 31;
    const int m0g = blockIdx.y * 128;
    const int n0g = blockIdx.x * 64;
    const int mw = (w & 3) * 32, nw = (w >> 2) * 32;
    const int frow = (lane & 7) + ((lane & 8) ? 8 : 0);
    const int fk   = (lane & 16) ? 16 : 0;
    const int brow = t >> 2, bc16 = t & 3;

    uint4 pah[2], pal[2], pbh, pbl;
    auto prefetch = [&](int kb) {
#pragma unroll
        for (int i = 0; i < 2; i++) {
            int idx = t + i * 256, row = idx >> 2, c16 = idx & 3;
            size_t o = (size_t)(m0g + row) * D_ + kb * 32 + c16 * 8;
            pah[i] = *(const uint4*)(g_xhi + o);
            pal[i] = *(const uint4*)(g_xlo + o);
        }
        size_t ob = (size_t)(n0g + brow) * D_ + kb * 32 + bc16 * 8;
        pbh = *(const uint4*)(g_Bhi + ob);
        pbl = *(const uint4*)(g_Blo + ob);
    };
    auto store_buf = [&](int buf) {
#pragma unroll
        for (int i = 0; i < 2; i++) {
            int idx = t + i * 256, row = idx >> 2, c16 = idx & 3;
            *(uint4*)(smem + XP_SM_A(buf, 0) + row * 80 + c16 * 16) = pah[i];
            *(uint4*)(smem + XP_SM_A(buf, 1) + row * 80 + c16 * 16) = pal[i];
        }
        *(uint4*)(smem + XP_SM_B(buf, 0) + brow * 80 + bc16 * 16) = pbh;
        *(uint4*)(smem + XP_SM_B(buf, 1) + brow * 80 + bc16 * 16) = pbl;
    };

    float ahh[32], amx[32];
#pragma unroll
    for (int i = 0; i < 32; i++) { ahh[i] = 0.f; amx[i] = 0.f; }

    prefetch(0); store_buf(0); __syncthreads();

    for (int kb = 0; kb < 16; kb++) {
        const int buf = kb & 1;
        if (kb + 1 < 16) prefetch(kb + 1);
        const uint32_t aH = sb + XP_SM_A(buf, 0), aL = sb + XP_SM_A(buf, 1);
        const uint32_t bH = sb + XP_SM_B(buf, 0), bL = sb + XP_SM_B(buf, 1);
#pragma unroll
        for (int ks = 0; ks < 2; ks++) {
            uint32_t fah[2][4], fal[2][4], fbh[2][4], fbl[2][4];
#pragma unroll
            for (int mi = 0; mi < 2; mi++) {
                ldm4(fah[mi], aH + (mw + mi * 16 + frow) * 80 + fk + ks * 32);
                ldm4(fal[mi], aL + (mw + mi * 16 + frow) * 80 + fk + ks * 32);
            }
#pragma unroll
            for (int ni = 0; ni < 2; ni++) {
                ldm4(fbh[ni], bH + (nw + ni * 16 + frow) * 80 + fk + ks * 32);
                ldm4(fbl[ni], bL + (nw + ni * 16 + frow) * 80 + fk + ks * 32);
            }
#pragma unroll
            for (int mi = 0; mi < 2; mi++)
#pragma unroll
                for (int ni = 0; ni < 2; ni++) {
                    float* ph = &ahh[(mi * 2 + ni) * 8];
                    float* pm = &amx[(mi * 2 + ni) * 8];
                    mma_bf16(ph,     fah[mi], fbh[ni][0], fbh[ni][2]);
                    mma_bf16(ph + 4, fah[mi], fbh[ni][1], fbh[ni][3]);
                    mma_bf16(pm,     fah[mi], fbl[ni][0], fbl[ni][2]);
                    mma_bf16(pm + 4, fah[mi], fbl[ni][1], fbl[ni][3]);
                    mma_bf16(pm,     fal[mi], fbh[ni][0], fbh[ni][2]);
                    mma_bf16(pm + 4, fal[mi], fbh[ni][1], fbh[ni][3]);
                }
        }
        if (kb + 1 < 16) { __syncthreads(); store_buf(buf ^ 1); __syncthreads(); }
    }

#pragma unroll
    for (int mi = 0; mi < 2; mi++)
#pragma unroll
        for (int ni = 0; ni < 2; ni++)
#pragma unroll
            for (int u = 0; u < 2; u++) {
                const float* ph = &ahh[(mi * 2 + ni) * 8 + u * 4];
                const float* pm = &amx[(mi * 2 + ni) * 8 + u * 4];
                size_t r0 = (size_t)(m0g + mw + mi * 16 + (lane >> 2));
                int    c0 = n0g + nw + ni * 16 + u * 8 + 2 * (lane & 3);
                *(float2*)(g_xp + r0 * 4096 + c0)       = make_float2(ph[0] + pm[0], ph[1] + pm[1]);
                *(float2*)(g_xp + (r0 + 8) * 4096 + c0) = make_float2(ph[2] + pm[2], ph[3] + pm[3]);
            }
}

// ---------------- persistent recurrence: fp16 1-term, A+W smem-resident ----
__global__ void __launch_bounds__(256, 1) lstm_persist(
    const float* __restrict__ bi, const float* __restrict__ bf,
    const float* __restrict__ bo, const float* __restrict__ bc)
{
    extern __shared__ __align__(128) char smem[];
    const uint32_t sb = smem_u32(smem);
    const int t    = threadIdx.x;
    const int w    = t >> 5;
    const int lane = t & 31;
    const int n0   = blockIdx.x * 32;

    // warp tile: m-half x n-half x k-half  (m32 n16 k512)
    const int mh = w >> 2, nh = (w >> 1) & 1, kh = w & 1;
    const int m0 = mh * 32;
    const int frow = (lane & 7) + ((lane & 8) ? 8 : 0);
    const int fk   = (lane & 16) ? 16 : 0;
    const uint32_t aBase = sb + SM_A + (uint32_t)(m0 + frow) * WS_STR + kh * 1024 + fk;
    const uint32_t wBase = sb + (uint32_t)(nh * 16 + frow) * WS_STR + kh * 1024 + fk;

    // ---- resident Wh fp16: 32 rows x 1024 k ----
#pragma unroll
    for (int i = 0; i < 16; i++) {
        int idx = t + i * 256;                    // 4096 16B chunks
        int row = idx >> 7, c16 = idx & 127;
        *(uint4*)(smem + row * WS_STR + c16 * 16) =
            *(const uint4*)(g_Wh16 + (size_t)(n0 + row) * H_ + c16 * 8);
    }

    const int hloc  = t & 7;                 // invariant under +256 (256 % 8 == 0)
    const int hglob = blockIdx.x * 8 + hloc;
    const float bvi = bi[hglob], bvf = bf[hglob], bvo = bo[hglob], bvc = bc[hglob];
    __syncthreads();

    for (int s = 0; s < S_; s++) {
        const int cur = s & 1;
        const __half* Hc = g_Hf[cur];

        // ---- stage A (full H, fp16) + xp via cp.async ----
#pragma unroll
        for (int i = 0; i < 32; i++) {
            int idx = t + i * 256;                // 8192 chunks
            int row = idx >> 7, c16 = idx & 127;
            cp16(sb + SM_A + row * WS_STR + c16 * 16, Hc + (size_t)row * H_ + c16 * 8);
        }
#pragma unroll
        for (int i = 0; i < 2; i++) {
            int idx = t + i * 256;                // 512 chunks of xp
            int br = idx >> 3, c = idx & 7;
            cp16(sb + SM_XP + idx * 16,
                 g_xp + ((size_t)s * B_ + br) * 4096 + n0 + c * 4);
        }
        asm volatile("cp.async.commit_group;" ::: "memory");
        asm volatile("cp.async.wait_group 0;" ::: "memory");
        __syncthreads();

        // ---- MMA: m32n16 x k512 per warp, single fp16 term ----
        float acc[16];
#pragma unroll
        for (int i = 0; i < 16; i++) acc[i] = 0.f;

#pragma unroll
        for (int ks = 0; ks < 32; ks++) {
            uint32_t a0[4], a1[4], bfr[4];
            ldm4(a0, aBase + ks * 32);
            ldm4(a1, aBase + 16 * WS_STR + ks * 32);
            ldm4(bfr, wBase + ks * 32);
            mma_f16(acc,      a0, bfr[0], bfr[2]);
            mma_f16(acc + 4,  a0, bfr[1], bfr[3]);
            mma_f16(acc + 8,  a1, bfr[0], bfr[2]);
            mma_f16(acc + 12, a1, bfr[1], bfr[3]);
        }

        // ---- store k-partials ----
        float* sg = (float*)(smem + SM_G + kh * 8448);
        {
            const int r = lane >> 2, cc = 2 * (lane & 3);
#pragma unroll
            for (int mi = 0; mi < 2; mi++)
#pragma unroll
                for (int ni = 0; ni < 2; ni++) {
                    const float* a = acc + (mi * 2 + ni) * 4;
                    int row = m0 + mi * 16 + r;
                    int col = nh * 16 + ni * 8 + cc;
                    sg[row * 33 + col]           = a[0];
                    sg[row * 33 + col + 1]       = a[1];
                    sg[(row + 8) * 33 + col]     = a[2];
                    sg[(row + 8) * 33 + col + 1] = a[3];
                }
        }
        __syncthreads();

        // ---- epilogue: 512 cells, 2 per thread (FIX: was 1 -> half batches) ----
        {
            const float* sg0 = (const float*)(smem + SM_G);
            const float* sg1 = (const float*)(smem + SM_G + 8448);
            const float* xps = (const float*)(smem + SM_XP);
            __half* Hn = g_Hf[cur ^ 1];
#pragma unroll
            for (int j = 0; j < 2; j++) {
                const int idx = t + j * 256;
                const int b   = idx >> 3;        // 0..63
                const int gbase = b * 33 + hloc * 4;
                float4 xv = *(const float4*)(xps + b * 32 + hloc * 4);
                float gi = sg0[gbase]     + sg1[gbase]     + xv.x + bvi;
                float gf = sg0[gbase + 1] + sg1[gbase + 1] + xv.y + bvf;
                float go = sg0[gbase + 2] + sg1[gbase + 2] + xv.z + bvo;
                float gc = sg0[gbase + 3] + sg1[gbase + 3] + xv.w + bvc;
                float iv = sigmoidf_(gi), fv = sigmoidf_(gf), ov = sigmoidf_(go);
                float cv = tanhf(gc);
                float cn = fv * g_C[b * H_ + hglob] + iv * cv;
                float hn = ov * tanhf(cn);
                g_C[b * H_ + hglob] = cn;
                Hn[b * H_ + hglob] = __float2half_rn(hn);
                g_outs[((size_t)s * B_ + b) * H_ + hglob] = hn;
            }
        }

        // ---- grid barrier ----
        __syncthreads();
        if (t == 0) {
            __threadfence();
            atomicAdd(&g_bar, 1u);
            const unsigned tgt = (unsigned)NCTA * (unsigned)(s + 1);
            while (*(volatile unsigned*)&g_bar < tgt) { }
            __threadfence();
        }
        __syncthreads();
    }
}

// ---------------- fc + finalize --------------------------------------------
__global__ void fc_kernel(const float* __restrict__ fcW,
                          const float* __restrict__ fcb,
                          float* __restrict__ pred)
{
    int gw = (blockIdx.x * blockDim.x + threadIdx.x) >> 5;
    int lane = threadIdx.x & 31;
    if (gw >= B_ * S_) return;
    int s = gw >> 6;
    int b = gw & 63;
    const float* row = g_outs + ((size_t)s * B_ + b) * H_;
    float sum = 0.0f;
#pragma unroll 4
    for (int h = lane; h < H_; h += 32) sum += row[h] * fcW[h];
#pragma unroll
    for (int o = 16; o; o >>= 1) sum += __shfl_down_sync(0xFFFFFFFFu, sum, o);
    if (lane == 0) pred[(size_t)b * S_ + s] = sum + fcb[0];
}

__global__ void finalize_kernel(float* __restrict__ out, int out_size) {
    int i = blockIdx.x * blockDim.x + threadIdx.x;
    if (i >= B_ * H_) return;
    const int PRED = B_ * S_;
    if (out_size >= PRED + B_ * H_)
        out[PRED + i] = g_outs[((size_t)(S_ - 1) * B_) * H_ + i];
    if (out_size >= PRED + 2 * B_ * H_)
        out[PRED + B_ * H_ + i] = g_C[i];
}

// ---------------------------------------------------------------------------
extern "C" void kernel_launch(void* const* d_in, const int* in_sizes, int n_in,
                              void* d_out, int out_size)
{
    const float* inputs = (const float*)d_in[0];
    const float* H0  = (const float*)d_in[1];
    const float* C0  = (const float*)d_in[2];
    const float* Wxi = (const float*)d_in[3];
    const float* Whi = (const float*)d_in[4];
    const float* bi  = (const float*)d_in[5];
    const float* Wxf = (const float*)d_in[6];
    const float* Whf = (const float*)d_in[7];
    const float* bf  = (const float*)d_in[8];
    const float* Wxo = (const float*)d_in[9];
    const float* Who = (const float*)d_in[10];
    const float* bo  = (const float*)d_in[11];
    const float* Wxc = (const float*)d_in[12];
    const float* Whc = (const float*)d_in[13];
    const float* bc  = (const float*)d_in[14];
    const float* fcW = (const float*)d_in[15];
    const float* fcb = (const float*)d_in[16];
    float* out = (float*)d_out;

    cudaFuncSetAttribute(lstm_persist, cudaFuncAttributeMaxDynamicSharedMemorySize, PSM_TOTAL);
    cudaFuncSetAttribute(xproj_gemm,  cudaFuncAttributeMaxDynamicSharedMemorySize, XP_SMEM);

    conv_x<<<4096, 256>>>(inputs);
    conv_W<<<3072, 256>>>(Wxi, Wxf, Wxo, Wxc, Whi, Whf, Who, Whc);
    lstm_init<<<(B_ * H_ + 255) / 256, 256>>>(H0, C0);

    xproj_gemm<<<dim3(64, 256), 256, XP_SMEM>>>();

    lstm_persist<<<NCTA, 256, PSM_TOTAL>>>(bi, bf, bo, bc);

    fc_kernel<<<(B_ * S_) / 8, 256>>>(fcW, fcb, out);
    finalize_kernel<<<(B_ * H_ + 255) / 256, 256>>>(out, out_size);
}

// round 12
// speedup vs baseline: 3.2802x; 1.4274x over previous
#include <cuda_runtime.h>
#include <cuda_fp16.h>
#include <math.h>
#include <stdint.h>

#define B_ 64
#define S_ 512
#define D_ 512
#define H_ 1024
#define NCTA 128           // persistent CTAs, 1/SM -> grid barrier safe

// ---- persistent kernel smem map (bytes) ----
#define WS_STR 2064                    // 1024 fp16 + 16B pad
#define SM_A   66048                   // weights: 32*2064
#define SM_G   198144                  // A: 64*2064 = 132096
#define SM_XP  215040                  // gates: 2 copies * 64*33*4 = 16896
#define PSM_TOTAL 223232               // + xp 8192

// ---- xproj kernel smem map (single term fp16) ----
#define XP_SM_A(buf) ((buf)*10240)          // 128 rows * 80 B
#define XP_SM_B(buf) (20480 + (buf)*5120)   // 64 rows * 80 B
#define XP_SMEM 30720

// ---------------- device scratch (allocation-free rule) -------------------
__device__ __half g_x16[(size_t)S_ * B_ * D_];      // [s][b][d] fp16
__device__ __half g_W16[(size_t)4096 * 1536];       // [n=h*4+g][k] fp16 (Wx|Wh)
__device__ float  g_xp[(size_t)S_ * B_ * 4096];     // x@Wx fp32
__device__ __half g_Hf[2][B_ * H_];                 // H state fp16
__device__ float  g_C[B_ * H_];
__device__ float  g_outs[(size_t)S_ * B_ * H_];     // [s][b][h]
__device__ unsigned g_bar;

// ---------------- helpers ---------------------------------------------------
__device__ __forceinline__ uint32_t smem_u32(const void* p) {
    uint32_t a;
    asm("{ .reg .u64 t; cvta.to.shared.u64 t, %1; cvt.u32.u64 %0, t; }" : "=r"(a) : "l"(p));
    return a;
}
__device__ __forceinline__ void ldm4(uint32_t* r, uint32_t addr) {
    asm volatile("ldmatrix.sync.aligned.m8n8.x4.shared.b16 {%0,%1,%2,%3}, [%4];"
                 : "=r"(r[0]), "=r"(r[1]), "=r"(r[2]), "=r"(r[3]) : "r"(addr));
}
__device__ __forceinline__ void mma_f16(float* d, const uint32_t* a, uint32_t b0, uint32_t b1) {
    asm volatile(
        "mma.sync.aligned.m16n8k16.row.col.f32.f16.f16.f32 "
        "{%0,%1,%2,%3}, {%4,%5,%6,%7}, {%8,%9}, {%0,%1,%2,%3};"
        : "+f"(d[0]), "+f"(d[1]), "+f"(d[2]), "+f"(d[3])
        : "r"(a[0]), "r"(a[1]), "r"(a[2]), "r"(a[3]), "r"(b0), "r"(b1));
}
__device__ __forceinline__ void cp16(uint32_t s, const void* g) {
    asm volatile("cp.async.cg.shared.global [%0], [%1], 16;" :: "r"(s), "l"(g));
}
__device__ __forceinline__ float sigmoidf_(float x) { return 1.0f / (1.0f + expf(-x)); }

// ---------------- conversion / init kernels --------------------------------
__global__ void conv_x(const float* __restrict__ x) {
    size_t n = (size_t)S_ * B_ * D_;
    for (size_t i = blockIdx.x * (size_t)blockDim.x + threadIdx.x; i < n;
         i += (size_t)gridDim.x * blockDim.x) {
        size_t s = i / (B_ * D_);
        size_t r = i % (B_ * D_);
        size_t b = r / D_, d = r % D_;
        g_x16[i] = __float2half_rn(x[(b * S_ + s) * D_ + d]);
    }
}

// tiled transpose: W[k][h] (fp32) -> g_W16[h*4+g][koff+k] (fp16), coalesced both ways
__global__ void conv_W_t(const float* __restrict__ Wxi, const float* __restrict__ Wxf,
                         const float* __restrict__ Wxo, const float* __restrict__ Wxc,
                         const float* __restrict__ Whi, const float* __restrict__ Whf,
                         const float* __restrict__ Who, const float* __restrict__ Whc)
{
    const int z = blockIdx.z;
    const int g = z & 3;
    const bool isWh = z >= 4;
    const int K = isWh ? 1024 : 512;
    const int koff = isWh ? 512 : 0;
    const int k0 = blockIdx.y * 32;
    if (k0 >= K) return;
    const int h0 = blockIdx.x * 32;
    const float* W =
        isWh ? ((g == 0) ? Whi : (g == 1) ? Whf : (g == 2) ? Who : Whc)
             : ((g == 0) ? Wxi : (g == 1) ? Wxf : (g == 2) ? Wxo : Wxc);

    __shared__ __half tile[32][33];
    const int tx = threadIdx.x, ty = threadIdx.y;
#pragma unroll
    for (int j = 0; j < 4; j++) {
        int kk = k0 + ty + j * 8;
        tile[ty + j * 8][tx] = __float2half_rn(W[(size_t)kk * H_ + h0 + tx]);
    }
    __syncthreads();
#pragma unroll
    for (int j = 0; j < 4; j++) {
        int hh = h0 + ty + j * 8;
        g_W16[(size_t)(hh * 4 + g) * 1536 + koff + k0 + tx] = tile[tx][ty + j * 8];
    }
}

__global__ void lstm_init(const float* __restrict__ H0, const float* __restrict__ C0) {
    int i = blockIdx.x * blockDim.x + threadIdx.x;
    if (i == 0) g_bar = 0u;
    if (i < B_ * H_) {
        g_Hf[0][i] = __float2half_rn(H0[i]);
        g_C[i] = C0[i];
    }
}

// ---------------- xproj: xp[32768][4096] = x @ Wx (fp16 1-term) ------------
__global__ void __launch_bounds__(256) xproj_gemm() {
    extern __shared__ __align__(128) char smem[];
    const uint32_t sb = smem_u32(smem);
    const int t = threadIdx.x, w = t >> 5, lane = t & 31;
    const int m0g = blockIdx.y * 128;
    const int n0g = blockIdx.x * 64;
    const int mw = (w & 3) * 32, nw = (w >> 2) * 32;
    const int frow = (lane & 7) + ((lane & 8) ? 8 : 0);
    const int fk   = (lane & 16) ? 16 : 0;
    const int brow = t >> 2, bc4 = t & 3;

    uint4 pa[2], pb;
    auto prefetch = [&](int kb) {
#pragma unroll
        for (int i = 0; i < 2; i++) {
            int idx = t + i * 256, row = idx >> 2, c4 = idx & 3;
            pa[i] = *(const uint4*)(g_x16 + (size_t)(m0g + row) * D_ + kb * 32 + c4 * 8);
        }
        pb = *(const uint4*)(g_W16 + (size_t)(n0g + brow) * 1536 + kb * 32 + bc4 * 8);
    };
    auto store_buf = [&](int buf) {
#pragma unroll
        for (int i = 0; i < 2; i++) {
            int idx = t + i * 256, row = idx >> 2, c4 = idx & 3;
            *(uint4*)(smem + XP_SM_A(buf) + row * 80 + c4 * 16) = pa[i];
        }
        *(uint4*)(smem + XP_SM_B(buf) + brow * 80 + bc4 * 16) = pb;
    };

    float acc[32];
#pragma unroll
    for (int i = 0; i < 32; i++) acc[i] = 0.f;

    prefetch(0); store_buf(0); __syncthreads();

    for (int kb = 0; kb < 16; kb++) {
        const int buf = kb & 1;
        if (kb + 1 < 16) prefetch(kb + 1);
        const uint32_t aB = sb + XP_SM_A(buf), bB = sb + XP_SM_B(buf);
#pragma unroll
        for (int ks = 0; ks < 2; ks++) {
            uint32_t fa[2][4], fb[2][4];
#pragma unroll
            for (int mi = 0; mi < 2; mi++)
                ldm4(fa[mi], aB + (mw + mi * 16 + frow) * 80 + fk + ks * 32);
#pragma unroll
            for (int ni = 0; ni < 2; ni++)
                ldm4(fb[ni], bB + (nw + ni * 16 + frow) * 80 + fk + ks * 32);
#pragma unroll
            for (int mi = 0; mi < 2; mi++)
#pragma unroll
                for (int ni = 0; ni < 2; ni++) {
                    float* p = &acc[(mi * 2 + ni) * 8];
                    mma_f16(p,     fa[mi], fb[ni][0], fb[ni][2]);
                    mma_f16(p + 4, fa[mi], fb[ni][1], fb[ni][3]);
                }
        }
        if (kb + 1 < 16) { __syncthreads(); store_buf(buf ^ 1); __syncthreads(); }
    }

#pragma unroll
    for (int mi = 0; mi < 2; mi++)
#pragma unroll
        for (int ni = 0; ni < 2; ni++)
#pragma unroll
            for (int u = 0; u < 2; u++) {
                const float* p = &acc[(mi * 2 + ni) * 8 + u * 4];
                size_t r0 = (size_t)(m0g + mw + mi * 16 + (lane >> 2));
                int    c0 = n0g + nw + ni * 16 + u * 8 + 2 * (lane & 3);
                *(float2*)(g_xp + r0 * 4096 + c0)       = make_float2(p[0], p[1]);
                *(float2*)(g_xp + (r0 + 8) * 4096 + c0) = make_float2(p[2], p[3]);
            }
}

// ---------------- persistent recurrence: fp16, pipelined staging -----------
__global__ void __launch_bounds__(256, 1) lstm_persist(
    const float* __restrict__ bi, const float* __restrict__ bf,
    const float* __restrict__ bo, const float* __restrict__ bc)
{
    extern __shared__ __align__(128) char smem[];
    const uint32_t sb = smem_u32(smem);
    const int t    = threadIdx.x;
    const int w    = t >> 5;
    const int lane = t & 31;
    const int n0   = blockIdx.x * 32;

    // warp tile: m-half x n-half x k-half  (m32 n16 k512)
    const int mh = w >> 2, nh = (w >> 1) & 1, kh = w & 1;
    const int m0 = mh * 32;
    const int frow = (lane & 7) + ((lane & 8) ? 8 : 0);
    const int fk   = (lane & 16) ? 16 : 0;
    const uint32_t aBase = sb + SM_A + (uint32_t)(m0 + frow) * WS_STR + kh * 1024 + fk;
    const uint32_t wBase = sb + (uint32_t)(nh * 16 + frow) * WS_STR + kh * 1024 + fk;

    // ---- resident Wh fp16: 32 rows x 1024 k (cols 512..1536 of g_W16) ----
#pragma unroll
    for (int i = 0; i < 16; i++) {
        int idx = t + i * 256;
        int row = idx >> 7, c16 = idx & 127;
        *(uint4*)(smem + row * WS_STR + c16 * 16) =
            *(const uint4*)(g_W16 + (size_t)(n0 + row) * 1536 + 512 + c16 * 8);
    }

    const int hloc  = t & 7;                 // invariant under +256
    const int hglob = blockIdx.x * 8 + hloc;
    const float bvi = bi[hglob], bvf = bf[hglob], bvo = bo[hglob], bvc = bc[hglob];
    __syncthreads();

    for (int s = 0; s < S_; s++) {
        const int cur = s & 1;
        const __half* Hc = g_Hf[cur];

        // ---- issue 4 staging chunks (each spans both k-halves) + xp -------
        // chunk c: c16 in [c*16, c*16+16) and [64+c*16, 64+c*16+16)
#pragma unroll
        for (int c = 0; c < 4; c++) {
            if (c == 0) {   // xp goes in group 0
#pragma unroll
                for (int i = 0; i < 2; i++) {
                    int idx = t + i * 256;
                    cp16(sb + SM_XP + idx * 16,
                         g_xp + ((size_t)s * B_ + (idx >> 3)) * 4096 + n0 + (idx & 7) * 4);
                }
            }
#pragma unroll
            for (int i = 0; i < 8; i++) {
                int idx = t + i * 256;             // 2048 chunks
                int row = idx >> 5, q = idx & 31;
                int c16 = ((q & 16) ? 64 : 0) + c * 16 + (q & 15);
                cp16(sb + SM_A + row * WS_STR + c16 * 16,
                     Hc + (size_t)row * H_ + c16 * 8);
            }
            asm volatile("cp.async.commit_group;" ::: "memory");
        }

        // ---- MMA over 4 chunks, overlapped with in-flight staging ---------
        float acc[16];
#pragma unroll
        for (int i = 0; i < 16; i++) acc[i] = 0.f;

#pragma unroll
        for (int c = 0; c < 4; c++) {
            switch (3 - c) {
                case 3: asm volatile("cp.async.wait_group 3;" ::: "memory"); break;
                case 2: asm volatile("cp.async.wait_group 2;" ::: "memory"); break;
                case 1: asm volatile("cp.async.wait_group 1;" ::: "memory"); break;
                default: asm volatile("cp.async.wait_group 0;" ::: "memory"); break;
            }
            __syncthreads();
#pragma unroll
            for (int ks = 0; ks < 8; ks++) {
                const uint32_t off = (c * 8 + ks) * 32;
                uint32_t a0[4], a1[4], bfr[4];
                ldm4(a0, aBase + off);
                ldm4(a1, aBase + 16 * WS_STR + off);
                ldm4(bfr, wBase + off);
                mma_f16(acc,      a0, bfr[0], bfr[2]);
                mma_f16(acc + 4,  a0, bfr[1], bfr[3]);
                mma_f16(acc + 8,  a1, bfr[0], bfr[2]);
                mma_f16(acc + 12, a1, bfr[1], bfr[3]);
            }
        }

        // ---- store k-partials ----
        __syncthreads();
        float* sg = (float*)(smem + SM_G + kh * 8448);
        {
            const int r = lane >> 2, cc = 2 * (lane & 3);
#pragma unroll
            for (int mi = 0; mi < 2; mi++)
#pragma unroll
                for (int ni = 0; ni < 2; ni++) {
                    const float* a = acc + (mi * 2 + ni) * 4;
                    int row = m0 + mi * 16 + r;
                    int col = nh * 16 + ni * 8 + cc;
                    sg[row * 33 + col]           = a[0];
                    sg[row * 33 + col + 1]       = a[1];
                    sg[(row + 8) * 33 + col]     = a[2];
                    sg[(row + 8) * 33 + col + 1] = a[3];
                }
        }
        __syncthreads();

        // ---- epilogue: 512 cells, 2 per thread ----
        {
            const float* sg0 = (const float*)(smem + SM_G);
            const float* sg1 = (const float*)(smem + SM_G + 8448);
            const float* xps = (const float*)(smem + SM_XP);
            __half* Hn = g_Hf[cur ^ 1];
#pragma unroll
            for (int j = 0; j < 2; j++) {
                const int idx = t + j * 256;
                const int b   = idx >> 3;
                const int gbase = b * 33 + hloc * 4;
                float4 xv = *(const float4*)(xps + b * 32 + hloc * 4);
                float gi = sg0[gbase]     + sg1[gbase]     + xv.x + bvi;
                float gf = sg0[gbase + 1] + sg1[gbase + 1] + xv.y + bvf;
                float go = sg0[gbase + 2] + sg1[gbase + 2] + xv.z + bvo;
                float gc = sg0[gbase + 3] + sg1[gbase + 3] + xv.w + bvc;
                float iv = sigmoidf_(gi), fv = sigmoidf_(gf), ov = sigmoidf_(go);
                float cv = tanhf(gc);
                float cn = fv * g_C[b * H_ + hglob] + iv * cv;
                float hn = ov * tanhf(cn);
                g_C[b * H_ + hglob] = cn;
                Hn[b * H_ + hglob] = __float2half_rn(hn);
                g_outs[((size_t)s * B_ + b) * H_ + hglob] = hn;
            }
        }

        // ---- grid barrier ----
        __syncthreads();
        if (t == 0) {
            __threadfence();
            atomicAdd(&g_bar, 1u);
            const unsigned tgt = (unsigned)NCTA * (unsigned)(s + 1);
            while (*(volatile unsigned*)&g_bar < tgt) { }
            __threadfence();
        }
        __syncthreads();
    }
}

// ---------------- fc + finalize --------------------------------------------
__global__ void fc_kernel(const float* __restrict__ fcW,
                          const float* __restrict__ fcb,
                          float* __restrict__ pred)
{
    int gw = (blockIdx.x * blockDim.x + threadIdx.x) >> 5;
    int lane = threadIdx.x & 31;
    if (gw >= B_ * S_) return;
    int s = gw >> 6;
    int b = gw & 63;
    const float* row = g_outs + ((size_t)s * B_ + b) * H_;
    float sum = 0.0f;
#pragma unroll 4
    for (int h = lane; h < H_; h += 32) sum += row[h] * fcW[h];
#pragma unroll
    for (int o = 16; o; o >>= 1) sum += __shfl_down_sync(0xFFFFFFFFu, sum, o);
    if (lane == 0) pred[(size_t)b * S_ + s] = sum + fcb[0];
}

__global__ void finalize_kernel(float* __restrict__ out, int out_size) {
    int i = blockIdx.x * blockDim.x + threadIdx.x;
    if (i >= B_ * H_) return;
    const int PRED = B_ * S_;
    if (out_size >= PRED + B_ * H_)
        out[PRED + i] = g_outs[((size_t)(S_ - 1) * B_) * H_ + i];
    if (out_size >= PRED + 2 * B_ * H_)
        out[PRED + B_ * H_ + i] = g_C[i];
}

// ---------------------------------------------------------------------------
extern "C" void kernel_launch(void* const* d_in, const int* in_sizes, int n_in,
                              void* d_out, int out_size)
{
    const float* inputs = (const float*)d_in[0];
    const float* H0  = (const float*)d_in[1];
    const float* C0  = (const float*)d_in[2];
    const float* Wxi = (const float*)d_in[3];
    const float* Whi = (const float*)d_in[4];
    const float* bi  = (const float*)d_in[5];
    const float* Wxf = (const float*)d_in[6];
    const float* Whf = (const float*)d_in[7];
    const float* bf  = (const float*)d_in[8];
    const float* Wxo = (const float*)d_in[9];
    const float* Who = (const float*)d_in[10];
    const float* bo  = (const float*)d_in[11];
    const float* Wxc = (const float*)d_in[12];
    const float* Whc = (const float*)d_in[13];
    const float* bc  = (const float*)d_in[14];
    const float* fcW = (const float*)d_in[15];
    const float* fcb = (const float*)d_in[16];
    float* out = (float*)d_out;

    cudaFuncSetAttribute(lstm_persist, cudaFuncAttributeMaxDynamicSharedMemorySize, PSM_TOTAL);
    cudaFuncSetAttribute(xproj_gemm,  cudaFuncAttributeMaxDynamicSharedMemorySize, XP_SMEM);

    conv_x<<<4096, 256>>>(inputs);
    conv_W_t<<<dim3(H_ / 32, 32, 8), dim3(32, 8)>>>(Wxi, Wxf, Wxo, Wxc,
                                                    Whi, Whf, Who, Whc);
    lstm_init<<<(B_ * H_ + 255) / 256, 256>>>(H0, C0);

    xproj_gemm<<<dim3(64, 256), 256, XP_SMEM>>>();

    lstm_persist<<<NCTA, 256, PSM_TOTAL>>>(bi, bf, bo, bc);

    fc_kernel<<<(B_ * S_) / 8, 256>>>(fcW, fcb, out);
    finalize_kernel<<<(B_ * H_ + 255) / 256, 256>>>(out, out_size);
}

// round 13
// speedup vs baseline: 3.3243x; 1.0134x over previous
#include <cuda_runtime.h>
#include <cuda_fp16.h>
#include <math.h>
#include <stdint.h>

#define B_ 64
#define S_ 512
#define D_ 512
#define H_ 1024
#define NCTA 128           // persistent CTAs, 1/SM -> grid barrier safe

// ---- persistent kernel smem map (bytes) ----
#define WS_STR 2064                    // 1024 fp16 + 16B pad
#define SM_A   66048                   // weights: 32*2064 at offset 0
#define SM_G   66048                   // gates overlay dead A region (4*8448=33792)
#define SM_XP  198144                  // A ends at 66048+132096
#define PSM_TOTAL 206336               // + xp 8192

// ---- xproj kernel smem map: ring-4, k64 chunks ----
#define XQ_A(buf) ((buf)*27648)            // A 128*144 = 18432
#define XQ_B(buf) ((buf)*27648 + 18432)    // B 64*144  = 9216
#define XP_SMEM 110592                     // 4 * 27648

// ---------------- device scratch (allocation-free rule) -------------------
__device__ __half g_x16[(size_t)S_ * B_ * D_];      // [s][b][d] fp16
__device__ __half g_W16[(size_t)4096 * 1536];       // [n=h*4+g][k] fp16 (Wx|Wh)
__device__ float  g_xp[(size_t)S_ * B_ * 4096];     // x@Wx fp32
__device__ __half g_Hf[2][B_ * H_];                 // H state fp16
__device__ float  g_C[B_ * H_];
__device__ float  g_outs[(size_t)S_ * B_ * H_];     // [s][b][h]
__device__ unsigned g_bar;

// ---------------- helpers ---------------------------------------------------
__device__ __forceinline__ uint32_t smem_u32(const void* p) {
    uint32_t a;
    asm("{ .reg .u64 t; cvta.to.shared.u64 t, %1; cvt.u32.u64 %0, t; }" : "=r"(a) : "l"(p));
    return a;
}
__device__ __forceinline__ void ldm4(uint32_t* r, uint32_t addr) {
    asm volatile("ldmatrix.sync.aligned.m8n8.x4.shared.b16 {%0,%1,%2,%3}, [%4];"
                 : "=r"(r[0]), "=r"(r[1]), "=r"(r[2]), "=r"(r[3]) : "r"(addr));
}
__device__ __forceinline__ void mma_f16(float* d, const uint32_t* a, uint32_t b0, uint32_t b1) {
    asm volatile(
        "mma.sync.aligned.m16n8k16.row.col.f32.f16.f16.f32 "
        "{%0,%1,%2,%3}, {%4,%5,%6,%7}, {%8,%9}, {%0,%1,%2,%3};"
        : "+f"(d[0]), "+f"(d[1]), "+f"(d[2]), "+f"(d[3])
        : "r"(a[0]), "r"(a[1]), "r"(a[2]), "r"(a[3]), "r"(b0), "r"(b1));
}
__device__ __forceinline__ void cp16(uint32_t s, const void* g) {
    asm volatile("cp.async.cg.shared.global [%0], [%1], 16;" :: "r"(s), "l"(g));
}
__device__ __forceinline__ float sigmoidf_(float x) { return 1.0f / (1.0f + expf(-x)); }

// ---------------- conversion / init kernels --------------------------------
__global__ void conv_x(const float* __restrict__ x) {
    size_t n = (size_t)S_ * B_ * D_;
    for (size_t i = blockIdx.x * (size_t)blockDim.x + threadIdx.x; i < n;
         i += (size_t)gridDim.x * blockDim.x) {
        size_t s = i / (B_ * D_);
        size_t r = i % (B_ * D_);
        size_t b = r / D_, d = r % D_;
        g_x16[i] = __float2half_rn(x[(b * S_ + s) * D_ + d]);
    }
}

// tiled transpose: W[k][h] (fp32) -> g_W16[h*4+g][koff+k] (fp16)
__global__ void conv_W_t(const float* __restrict__ Wxi, const float* __restrict__ Wxf,
                         const float* __restrict__ Wxo, const float* __restrict__ Wxc,
                         const float* __restrict__ Whi, const float* __restrict__ Whf,
                         const float* __restrict__ Who, const float* __restrict__ Whc)
{
    const int z = blockIdx.z;
    const int g = z & 3;
    const bool isWh = z >= 4;
    const int K = isWh ? 1024 : 512;
    const int koff = isWh ? 512 : 0;
    const int k0 = blockIdx.y * 32;
    if (k0 >= K) return;
    const int h0 = blockIdx.x * 32;
    const float* W =
        isWh ? ((g == 0) ? Whi : (g == 1) ? Whf : (g == 2) ? Who : Whc)
             : ((g == 0) ? Wxi : (g == 1) ? Wxf : (g == 2) ? Wxo : Wxc);

    __shared__ __half tile[32][33];
    const int tx = threadIdx.x, ty = threadIdx.y;
#pragma unroll
    for (int j = 0; j < 4; j++) {
        int kk = k0 + ty + j * 8;
        tile[ty + j * 8][tx] = __float2half_rn(W[(size_t)kk * H_ + h0 + tx]);
    }
    __syncthreads();
#pragma unroll
    for (int j = 0; j < 4; j++) {
        int hh = h0 + ty + j * 8;
        g_W16[(size_t)(hh * 4 + g) * 1536 + koff + k0 + tx] = tile[tx][ty + j * 8];
    }
}

__global__ void lstm_init(const float* __restrict__ H0, const float* __restrict__ C0) {
    int i = blockIdx.x * blockDim.x + threadIdx.x;
    if (i == 0) g_bar = 0u;
    if (i < B_ * H_) {
        g_Hf[0][i] = __float2half_rn(H0[i]);
        g_C[i] = C0[i];
    }
}

// ---------------- xproj: cp.async ring-4, k64 chunks -----------------------
__global__ void __launch_bounds__(256) xproj_gemm() {
    extern __shared__ __align__(128) char smem[];
    const uint32_t sb = smem_u32(smem);
    const int t = threadIdx.x, w = t >> 5, lane = t & 31;
    const int m0g = blockIdx.y * 128;
    const int n0g = blockIdx.x * 64;
    const int mw = (w & 3) * 32, nw = (w >> 2) * 32;
    const int frow = (lane & 7) + ((lane & 8) ? 8 : 0);
    const int fk   = (lane & 16) ? 16 : 0;

    auto stage = [&](int kb, int buf) {
#pragma unroll
        for (int i = 0; i < 4; i++) {              // A: 1024 cp16
            int idx = t + i * 256;
            int row = idx >> 3, c = idx & 7;
            cp16(sb + XQ_A(buf) + row * 144 + c * 16,
                 g_x16 + (size_t)(m0g + row) * D_ + kb * 64 + c * 8);
        }
#pragma unroll
        for (int i = 0; i < 2; i++) {              // B: 512 cp16
            int idx = t + i * 256;
            int row = idx >> 3, c = idx & 7;
            cp16(sb + XQ_B(buf) + row * 144 + c * 16,
                 g_W16 + (size_t)(n0g + row) * 1536 + kb * 64 + c * 8);
        }
        asm volatile("cp.async.commit_group;" ::: "memory");
    };

    float acc[32];
#pragma unroll
    for (int i = 0; i < 32; i++) acc[i] = 0.f;

    stage(0, 0); stage(1, 1); stage(2, 2);

    for (int kb = 0; kb < 8; kb++) {
        const int buf = kb & 3;
        const int rem = 7 - kb;
        if (rem >= 2)      asm volatile("cp.async.wait_group 2;" ::: "memory");
        else if (rem == 1) asm volatile("cp.async.wait_group 1;" ::: "memory");
        else               asm volatile("cp.async.wait_group 0;" ::: "memory");
        __syncthreads();

        const uint32_t aB = sb + XQ_A(buf), bB = sb + XQ_B(buf);
#pragma unroll
        for (int ks = 0; ks < 4; ks++) {
            uint32_t fa[2][4], fb[2][4];
#pragma unroll
            for (int mi = 0; mi < 2; mi++)
                ldm4(fa[mi], aB + (mw + mi * 16 + frow) * 144 + fk + ks * 32);
#pragma unroll
            for (int ni = 0; ni < 2; ni++)
                ldm4(fb[ni], bB + (nw + ni * 16 + frow) * 144 + fk + ks * 32);
#pragma unroll
            for (int mi = 0; mi < 2; mi++)
#pragma unroll
                for (int ni = 0; ni < 2; ni++) {
                    float* p = &acc[(mi * 2 + ni) * 8];
                    mma_f16(p,     fa[mi], fb[ni][0], fb[ni][2]);
                    mma_f16(p + 4, fa[mi], fb[ni][1], fb[ni][3]);
                }
        }
        if (kb + 3 < 8) stage(kb + 3, (kb + 3) & 3);
    }

#pragma unroll
    for (int mi = 0; mi < 2; mi++)
#pragma unroll
        for (int ni = 0; ni < 2; ni++)
#pragma unroll
            for (int u = 0; u < 2; u++) {
                const float* p = &acc[(mi * 2 + ni) * 8 + u * 4];
                size_t r0 = (size_t)(m0g + mw + mi * 16 + (lane >> 2));
                int    c0 = n0g + nw + ni * 16 + u * 8 + 2 * (lane & 3);
                *(float2*)(g_xp + r0 * 4096 + c0)       = make_float2(p[0], p[1]);
                *(float2*)(g_xp + (r0 + 8) * 4096 + c0) = make_float2(p[2], p[3]);
            }
}

// ---------------- persistent recurrence: 2 m-halves x 4 k-quarters ---------
__global__ void __launch_bounds__(256, 1) lstm_persist(
    const float* __restrict__ bi, const float* __restrict__ bf,
    const float* __restrict__ bo, const float* __restrict__ bc)
{
    extern __shared__ __align__(128) char smem[];
    const uint32_t sb = smem_u32(smem);
    const int t    = threadIdx.x;
    const int w    = t >> 5;
    const int lane = t & 31;
    const int n0   = blockIdx.x * 32;

    // warp tile: m-half x k-quarter; warp covers m32 n32 k256
    const int mh = w & 1, kq = w >> 1;
    const int m0 = mh * 32;
    const int frow = (lane & 7) + ((lane & 8) ? 8 : 0);
    const int fk   = (lane & 16) ? 16 : 0;
    const uint32_t aBase = sb + SM_A + (uint32_t)(m0 + frow) * WS_STR + kq * 512 + fk;
    const uint32_t wB0   = sb + (uint32_t)(frow) * WS_STR      + kq * 512 + fk;
    const uint32_t wB16  = sb + (uint32_t)(16 + frow) * WS_STR + kq * 512 + fk;

    // ---- resident Wh fp16: 32 rows x 1024 k (cols 512..1536 of g_W16) ----
#pragma unroll
    for (int i = 0; i < 16; i++) {
        int idx = t + i * 256;
        int row = idx >> 7, c16 = idx & 127;
        *(uint4*)(smem + row * WS_STR + c16 * 16) =
            *(const uint4*)(g_W16 + (size_t)(n0 + row) * 1536 + 512 + c16 * 8);
    }

    const int hloc  = t & 7;                 // invariant under +256
    const int hglob = blockIdx.x * 8 + hloc;
    const float bvi = bi[hglob], bvf = bf[hglob], bvo = bo[hglob], bvc = bc[hglob];
    __syncthreads();

    for (int s = 0; s < S_; s++) {
        const int cur = s & 1;
        const __half* Hc = g_Hf[cur];

        // ---- issue 4 staging chunks; chunk c delivers 8 c16 per k-quarter --
#pragma unroll
        for (int c = 0; c < 4; c++) {
            if (c == 0) {   // xp rides in group 0
#pragma unroll
                for (int i = 0; i < 2; i++) {
                    int idx = t + i * 256;
                    cp16(sb + SM_XP + idx * 16,
                         g_xp + ((size_t)s * B_ + (idx >> 3)) * 4096 + n0 + (idx & 7) * 4);
                }
            }
#pragma unroll
            for (int i = 0; i < 8; i++) {
                int idx = t + i * 256;             // 2048 chunks
                int row = idx >> 5, q = idx & 31;
                int c16 = (q >> 3) * 32 + c * 8 + (q & 7);
                cp16(sb + SM_A + row * WS_STR + c16 * 16,
                     Hc + (size_t)row * H_ + c16 * 8);
            }
            asm volatile("cp.async.commit_group;" ::: "memory");
        }

        // ---- MMA: per chunk, each warp does 4 ks of its quarter ------------
        float acc[32];
#pragma unroll
        for (int i = 0; i < 32; i++) acc[i] = 0.f;

#pragma unroll
        for (int c = 0; c < 4; c++) {
            switch (3 - c) {
                case 3: asm volatile("cp.async.wait_group 3;" ::: "memory"); break;
                case 2: asm volatile("cp.async.wait_group 2;" ::: "memory"); break;
                case 1: asm volatile("cp.async.wait_group 1;" ::: "memory"); break;
                default: asm volatile("cp.async.wait_group 0;" ::: "memory"); break;
            }
            __syncthreads();
#pragma unroll
            for (int ks = 0; ks < 4; ks++) {
                const uint32_t off = c * 128 + ks * 32;
                uint32_t a0[4], a1[4], b0[4], b1[4];
                ldm4(a0, aBase + off);
                ldm4(a1, aBase + 16 * WS_STR + off);
                ldm4(b0, wB0 + off);
                ldm4(b1, wB16 + off);
                mma_f16(acc,      a0, b0[0], b0[2]);
                mma_f16(acc + 4,  a0, b0[1], b0[3]);
                mma_f16(acc + 8,  a0, b1[0], b1[2]);
                mma_f16(acc + 12, a0, b1[1], b1[3]);
                mma_f16(acc + 16, a1, b0[0], b0[2]);
                mma_f16(acc + 20, a1, b0[1], b0[3]);
                mma_f16(acc + 24, a1, b1[0], b1[2]);
                mma_f16(acc + 28, a1, b1[1], b1[3]);
            }
        }

        // ---- store k-partials (gates overlay dead A region) ----
        __syncthreads();
        float* sg = (float*)(smem + SM_G + kq * 8448);
        {
            const int r = lane >> 2, cc = 2 * (lane & 3);
#pragma unroll
            for (int mi = 0; mi < 2; mi++)
#pragma unroll
                for (int nq = 0; nq < 4; nq++) {
                    const float* a = acc + mi * 16 + nq * 4;
                    int row = m0 + mi * 16 + r;
                    int col = nq * 8 + cc;
                    sg[row * 33 + col]           = a[0];
                    sg[row * 33 + col + 1]       = a[1];
                    sg[(row + 8) * 33 + col]     = a[2];
                    sg[(row + 8) * 33 + col + 1] = a[3];
                }
        }
        __syncthreads();

        // ---- epilogue: 512 cells, 2 per thread, sum 4 k-partials ----
        {
            const float* sg0 = (const float*)(smem + SM_G);
            const float* sg1 = (const float*)(smem + SM_G + 8448);
            const float* sg2 = (const float*)(smem + SM_G + 16896);
            const float* sg3 = (const float*)(smem + SM_G + 25344);
            const float* xps = (const float*)(smem + SM_XP);
            __half* Hn = g_Hf[cur ^ 1];
#pragma unroll
            for (int j = 0; j < 2; j++) {
                const int idx = t + j * 256;
                const int b   = idx >> 3;
                const int gb  = b * 33 + hloc * 4;
                float4 xv = *(const float4*)(xps + b * 32 + hloc * 4);
                float gi = sg0[gb]   + sg1[gb]   + sg2[gb]   + sg3[gb]   + xv.x + bvi;
                float gf = sg0[gb+1] + sg1[gb+1] + sg2[gb+1] + sg3[gb+1] + xv.y + bvf;
                float go = sg0[gb+2] + sg1[gb+2] + sg2[gb+2] + sg3[gb+2] + xv.z + bvo;
                float gc = sg0[gb+3] + sg1[gb+3] + sg2[gb+3] + sg3[gb+3] + xv.w + bvc;
                float iv = sigmoidf_(gi), fv = sigmoidf_(gf), ov = sigmoidf_(go);
                float cv = tanhf(gc);
                float cn = fv * g_C[b * H_ + hglob] + iv * cv;
                float hn = ov * tanhf(cn);
                g_C[b * H_ + hglob] = cn;
                Hn[b * H_ + hglob] = __float2half_rn(hn);
                g_outs[((size_t)s * B_ + b) * H_ + hglob] = hn;
            }
        }

        // ---- grid barrier ----
        __syncthreads();
        if (t == 0) {
            __threadfence();
            atomicAdd(&g_bar, 1u);
            const unsigned tgt = (unsigned)NCTA * (unsigned)(s + 1);
            while (*(volatile unsigned*)&g_bar < tgt) { }
            __threadfence();
        }
        __syncthreads();
    }
}

// ---------------- fc + finalize --------------------------------------------
__global__ void fc_kernel(const float* __restrict__ fcW,
                          const float* __restrict__ fcb,
                          float* __restrict__ pred)
{
    int gw = (blockIdx.x * blockDim.x + threadIdx.x) >> 5;
    int lane = threadIdx.x & 31;
    if (gw >= B_ * S_) return;
    int s = gw >> 6;
    int b = gw & 63;
    const float* row = g_outs + ((size_t)s * B_ + b) * H_;
    float sum = 0.0f;
#pragma unroll 4
    for (int h = lane; h < H_; h += 32) sum += row[h] * fcW[h];
#pragma unroll
    for (int o = 16; o; o >>= 1) sum += __shfl_down_sync(0xFFFFFFFFu, sum, o);
    if (lane == 0) pred[(size_t)b * S_ + s] = sum + fcb[0];
}

__global__ void finalize_kernel(float* __restrict__ out, int out_size) {
    int i = blockIdx.x * blockDim.x + threadIdx.x;
    if (i >= B_ * H_) return;
    const int PRED = B_ * S_;
    if (out_size >= PRED + B_ * H_)
        out[PRED + i] = g_outs[((size_t)(S_ - 1) * B_) * H_ + i];
    if (out_size >= PRED + 2 * B_ * H_)
        out[PRED + B_ * H_ + i] = g_C[i];
}

// ---------------------------------------------------------------------------
extern "C" void kernel_launch(void* const* d_in, const int* in_sizes, int n_in,
                              void* d_out, int out_size)
{
    const float* inputs = (const float*)d_in[0];
    const float* H0  = (const float*)d_in[1];
    const float* C0  = (const float*)d_in[2];
    const float* Wxi = (const float*)d_in[3];
    const float* Whi = (const float*)d_in[4];
    const float* bi  = (const float*)d_in[5];
    const float* Wxf = (const float*)d_in[6];
    const float* Whf = (const float*)d_in[7];
    const float* bf  = (const float*)d_in[8];
    const float* Wxo = (const float*)d_in[9];
    const float* Who = (const float*)d_in[10];
    const float* bo  = (const float*)d_in[11];
    const float* Wxc = (const float*)d_in[12];
    const float* Whc = (const float*)d_in[13];
    const float* bc  = (const float*)d_in[14];
    const float* fcW = (const float*)d_in[15];
    const float* fcb = (const float*)d_in[16];
    float* out = (float*)d_out;

    cudaFuncSetAttribute(lstm_persist, cudaFuncAttributeMaxDynamicSharedMemorySize, PSM_TOTAL);
    cudaFuncSetAttribute(xproj_gemm,  cudaFuncAttributeMaxDynamicSharedMemorySize, XP_SMEM);

    conv_x<<<4096, 256>>>(inputs);
    conv_W_t<<<dim3(H_ / 32, 32, 8), dim3(32, 8)>>>(Wxi, Wxf, Wxo, Wxc,
                                                    Whi, Whf, Who, Whc);
    lstm_init<<<(B_ * H_ + 255) / 256, 256>>>(H0, C0);

    xproj_gemm<<<dim3(64, 256), 256, XP_SMEM>>>();

    lstm_persist<<<NCTA, 256, PSM_TOTAL>>>(bi, bf, bo, bc);

    fc_kernel<<<(B_ * S_) / 8, 256>>>(fcW, fcb, out);
    finalize_kernel<<<(B_ * H_ + 255) / 256, 256>>>(out, out_size);
}

// round 15
// speedup vs baseline: 3.9711x; 1.1946x over previous
#include <cuda_runtime.h>
#include <cuda_fp16.h>
#include <math.h>
#include <stdint.h>

#define B_ 64
#define S_ 512
#define D_ 512
#define H_ 1024
#define NCTA 128           // 2 groups x 64 CTAs, all resident (<=148 SMs)

// ---- persist smem map (bytes): W[64 rows] | A[32 rows] | xp ----
#define WS_STR 2064                    // 1024 fp16 + 16B pad
#define SM_A   132096                  // W: 64*2064
#define SM_G   132096                  // gates overlay A (4*8704=34816 <= 66048)
#define SM_XP  198144                  // A ends here
#define PSM_TOTAL 202240               // + xp 32*64*2 = 4096
#define GSTR   68                      // gate row stride (floats, 16B-aligned)

// ---- xproj kernel smem map: ring-4, k64 chunks ----
#define XQ_A(buf) ((buf)*27648)            // A 128*144 = 18432
#define XQ_B(buf) ((buf)*27648 + 18432)    // B 64*144  = 9216
#define XP_SMEM 110592                     // 4 * 27648

// ---------------- device scratch (allocation-free rule) -------------------
__device__ __half g_x16[(size_t)S_ * B_ * D_];      // [s][b][d] fp16
__device__ __half g_W16[(size_t)4096 * 1536];       // [n=h*4+g][k] fp16 (Wx|Wh)
__device__ __half g_xp16[(size_t)S_ * B_ * 4096];   // x@Wx fp16
__device__ __half g_Hf[2][B_ * H_];                 // H state fp16
__device__ float  g_C[B_ * H_];
__device__ float  g_outs[(size_t)S_ * B_ * H_];     // [s][b][h]
__device__ unsigned g_bars[64];                     // grp 0 at [0], grp 1 at [32]

// ---------------- helpers ---------------------------------------------------
__device__ __forceinline__ uint32_t smem_u32(const void* p) {
    uint32_t a;
    asm("{ .reg .u64 t; cvta.to.shared.u64 t, %1; cvt.u32.u64 %0, t; }" : "=r"(a) : "l"(p));
    return a;
}
__device__ __forceinline__ void ldm4(uint32_t* r, uint32_t addr) {
    asm volatile("ldmatrix.sync.aligned.m8n8.x4.shared.b16 {%0,%1,%2,%3}, [%4];"
                 : "=r"(r[0]), "=r"(r[1]), "=r"(r[2]), "=r"(r[3]) : "r"(addr));
}
__device__ __forceinline__ void mma_f16(float* d, const uint32_t* a, uint32_t b0, uint32_t b1) {
    asm volatile(
        "mma.sync.aligned.m16n8k16.row.col.f32.f16.f16.f32 "
        "{%0,%1,%2,%3}, {%4,%5,%6,%7}, {%8,%9}, {%0,%1,%2,%3};"
        : "+f"(d[0]), "+f"(d[1]), "+f"(d[2]), "+f"(d[3])
        : "r"(a[0]), "r"(a[1]), "r"(a[2]), "r"(a[3]), "r"(b0), "r"(b1));
}
__device__ __forceinline__ void cp16(uint32_t s, const void* g) {
    asm volatile("cp.async.cg.shared.global [%0], [%1], 16;" :: "r"(s), "l"(g));
}
__device__ __forceinline__ float sigmoid_f(float x) {
    return __fdividef(1.0f, 1.0f + __expf(-x));
}
__device__ __forceinline__ float tanh_f(float x) {
    float e = __expf(2.0f * x);
    return __fdividef(e - 1.0f, e + 1.0f);
}

// ---------------- conversion / init kernels --------------------------------
__global__ void conv_x(const float* __restrict__ x) {
    size_t n = (size_t)S_ * B_ * D_;
    for (size_t i = blockIdx.x * (size_t)blockDim.x + threadIdx.x; i < n;
         i += (size_t)gridDim.x * blockDim.x) {
        size_t s = i / (B_ * D_);
        size_t r = i % (B_ * D_);
        size_t b = r / D_, d = r % D_;
        g_x16[i] = __float2half_rn(x[(b * S_ + s) * D_ + d]);
    }
}

// tiled transpose: W[k][h] (fp32) -> g_W16[h*4+g][koff+k] (fp16)
__global__ void conv_W_t(const float* __restrict__ Wxi, const float* __restrict__ Wxf,
                         const float* __restrict__ Wxo, const float* __restrict__ Wxc,
                         const float* __restrict__ Whi, const float* __restrict__ Whf,
                         const float* __restrict__ Who, const float* __restrict__ Whc)
{
    const int z = blockIdx.z;
    const int g = z & 3;
    const bool isWh = z >= 4;
    const int K = isWh ? 1024 : 512;
    const int koff = isWh ? 512 : 0;
    const int k0 = blockIdx.y * 32;
    if (k0 >= K) return;
    const int h0 = blockIdx.x * 32;
    const float* W =
        isWh ? ((g == 0) ? Whi : (g == 1) ? Whf : (g == 2) ? Who : Whc)
             : ((g == 0) ? Wxi : (g == 1) ? Wxf : (g == 2) ? Wxo : Wxc);

    __shared__ __half tile[32][33];
    const int tx = threadIdx.x, ty = threadIdx.y;
#pragma unroll
    for (int j = 0; j < 4; j++) {
        int kk = k0 + ty + j * 8;
        tile[ty + j * 8][tx] = __float2half_rn(W[(size_t)kk * H_ + h0 + tx]);
    }
    __syncthreads();
#pragma unroll
    for (int j = 0; j < 4; j++) {
        int hh = h0 + ty + j * 8;
        g_W16[(size_t)(hh * 4 + g) * 1536 + koff + k0 + tx] = tile[tx][ty + j * 8];
    }
}

__global__ void lstm_init(const float* __restrict__ H0, const float* __restrict__ C0) {
    int i = blockIdx.x * blockDim.x + threadIdx.x;
    if (i < 64) g_bars[i] = 0u;
    if (i < B_ * H_) {
        g_Hf[0][i] = __float2half_rn(H0[i]);
        g_C[i] = C0[i];
    }
}

// ---------------- xproj: cp.async ring-4, fp16 output ----------------------
__global__ void __launch_bounds__(256) xproj_gemm() {
    extern __shared__ __align__(128) char smem[];
    const uint32_t sb = smem_u32(smem);
    const int t = threadIdx.x, w = t >> 5, lane = t & 31;
    const int m0g = blockIdx.y * 128;
    const int n0g = blockIdx.x * 64;
    const int mw = (w & 3) * 32, nw = (w >> 2) * 32;
    const int frow = (lane & 7) + ((lane & 8) ? 8 : 0);
    const int fk   = (lane & 16) ? 16 : 0;

    auto stage = [&](int kb, int buf) {
#pragma unroll
        for (int i = 0; i < 4; i++) {
            int idx = t + i * 256;
            int row = idx >> 3, c = idx & 7;
            cp16(sb + XQ_A(buf) + row * 144 + c * 16,
                 g_x16 + (size_t)(m0g + row) * D_ + kb * 64 + c * 8);
        }
#pragma unroll
        for (int i = 0; i < 2; i++) {
            int idx = t + i * 256;
            int row = idx >> 3, c = idx & 7;
            cp16(sb + XQ_B(buf) + row * 144 + c * 16,
                 g_W16 + (size_t)(n0g + row) * 1536 + kb * 64 + c * 8);
        }
        asm volatile("cp.async.commit_group;" ::: "memory");
    };

    float acc[32];
#pragma unroll
    for (int i = 0; i < 32; i++) acc[i] = 0.f;

    stage(0, 0); stage(1, 1); stage(2, 2);

    for (int kb = 0; kb < 8; kb++) {
        const int buf = kb & 3;
        const int rem = 7 - kb;
        if (rem >= 2)      asm volatile("cp.async.wait_group 2;" ::: "memory");
        else if (rem == 1) asm volatile("cp.async.wait_group 1;" ::: "memory");
        else               asm volatile("cp.async.wait_group 0;" ::: "memory");
        __syncthreads();

        const uint32_t aB = sb + XQ_A(buf), bB = sb + XQ_B(buf);
#pragma unroll
        for (int ks = 0; ks < 4; ks++) {
            uint32_t fa[2][4], fb[2][4];
#pragma unroll
            for (int mi = 0; mi < 2; mi++)
                ldm4(fa[mi], aB + (mw + mi * 16 + frow) * 144 + fk + ks * 32);
#pragma unroll
            for (int ni = 0; ni < 2; ni++)
                ldm4(fb[ni], bB + (nw + ni * 16 + frow) * 144 + fk + ks * 32);
#pragma unroll
            for (int mi = 0; mi < 2; mi++)
#pragma unroll
                for (int ni = 0; ni < 2; ni++) {
                    float* p = &acc[(mi * 2 + ni) * 8];
                    mma_f16(p,     fa[mi], fb[ni][0], fb[ni][2]);
                    mma_f16(p + 4, fa[mi], fb[ni][1], fb[ni][3]);
                }
        }
        if (kb + 3 < 8) stage(kb + 3, (kb + 3) & 3);
    }

#pragma unroll
    for (int mi = 0; mi < 2; mi++)
#pragma unroll
        for (int ni = 0; ni < 2; ni++)
#pragma unroll
            for (int u = 0; u < 2; u++) {
                const float* p = &acc[(mi * 2 + ni) * 8 + u * 4];
                size_t r0 = (size_t)(m0g + mw + mi * 16 + (lane >> 2));
                int    c0 = n0g + nw + ni * 16 + u * 8 + 2 * (lane & 3);
                *(__half2*)(g_xp16 + r0 * 4096 + c0)       = __floats2half2_rn(p[0], p[1]);
                *(__half2*)(g_xp16 + (r0 + 8) * 4096 + c0) = __floats2half2_rn(p[2], p[3]);
            }
}

// ---------------- persistent recurrence: 2 batch groups, M=32 N=64 ---------
__global__ void __launch_bounds__(256, 1) lstm_persist(
    const float* __restrict__ bi, const float* __restrict__ bf,
    const float* __restrict__ bo, const float* __restrict__ bc)
{
    extern __shared__ __align__(128) char smem[];
    const uint32_t sb = smem_u32(smem);
    const int t    = threadIdx.x;
    const int w    = t >> 5;
    const int lane = t & 31;

    const int bg     = blockIdx.x & 1;          // batch group (0: b 0-31, 1: b 32-63)
    const int nslice = blockIdx.x >> 1;         // 0..63
    const int bofs   = bg * 32;
    const int n0     = nslice * 64;             // gate-row base

    // warp tile: k-quarter x n-half; warp covers m32 n32 k256
    const int kq = w >> 1, nq = w & 1;
    const int frow = (lane & 7) + ((lane & 8) ? 8 : 0);
    const int fk   = (lane & 16) ? 16 : 0;
    const uint32_t aBase = sb + SM_A + (uint32_t)frow * WS_STR + kq * 512 + fk;
    const uint32_t wB0   = sb + (uint32_t)(nq * 32 + frow) * WS_STR      + kq * 512 + fk;
    const uint32_t wB16  = sb + (uint32_t)(nq * 32 + 16 + frow) * WS_STR + kq * 512 + fk;

    // ---- resident Wh fp16: 64 gate rows x 1024 k ----
#pragma unroll
    for (int i = 0; i < 32; i++) {
        int idx = t + i * 256;
        int row = idx >> 7, c16 = idx & 127;
        *(uint4*)(smem + row * WS_STR + c16 * 16) =
            *(const uint4*)(g_W16 + (size_t)(n0 + row) * 1536 + 512 + c16 * 8);
    }

    const int hl    = t & 15;                // invariant under +256
    const int hglob = nslice * 16 + hl;
    const float bvi = bi[hglob], bvf = bf[hglob], bvo = bo[hglob], bvc = bc[hglob];
    unsigned* barp = &g_bars[bg * 32];
    __syncthreads();

    for (int s = 0; s < S_; s++) {
        const int cur = s & 1;
        const __half* Hc = g_Hf[cur] + bofs * H_;

        // ---- issue 4 staging chunks; chunk c gives each k-quarter 8 c16 ----
#pragma unroll
        for (int c = 0; c < 4; c++) {
            if (c == 0) {   // xp (fp16, 4 KB) rides in group 0
                cp16(sb + SM_XP + t * 16,
                     g_xp16 + ((size_t)s * B_ + bofs + (t >> 3)) * 4096 + n0 + (t & 7) * 8);
            }
#pragma unroll
            for (int i = 0; i < 4; i++) {
                int idx = t + i * 256;             // 1024 chunks
                int row = idx >> 5, q = idx & 31;
                int c16 = (q >> 3) * 32 + c * 8 + (q & 7);
                cp16(sb + SM_A + row * WS_STR + c16 * 16,
                     Hc + (size_t)row * H_ + c16 * 8);
            }
            asm volatile("cp.async.commit_group;" ::: "memory");
        }

        // ---- MMA: per chunk each warp does 4 ks of its k-quarter -----------
        float acc[32];
#pragma unroll
        for (int i = 0; i < 32; i++) acc[i] = 0.f;

#pragma unroll
        for (int c = 0; c < 4; c++) {
            switch (3 - c) {
                case 3: asm volatile("cp.async.wait_group 3;" ::: "memory"); break;
                case 2: asm volatile("cp.async.wait_group 2;" ::: "memory"); break;
                case 1: asm volatile("cp.async.wait_group 1;" ::: "memory"); break;
                default: asm volatile("cp.async.wait_group 0;" ::: "memory"); break;
            }
            __syncthreads();
#pragma unroll
            for (int ks = 0; ks < 4; ks++) {
                const uint32_t off = c * 128 + ks * 32;
                uint32_t a0[4], a1[4], b0[4], b1[4];
                ldm4(a0, aBase + off);
                ldm4(a1, aBase + 16 * WS_STR + off);
                ldm4(b0, wB0 + off);
                ldm4(b1, wB16 + off);
                mma_f16(acc,      a0, b0[0], b0[2]);
                mma_f16(acc + 4,  a0, b0[1], b0[3]);
                mma_f16(acc + 8,  a0, b1[0], b1[2]);
                mma_f16(acc + 12, a0, b1[1], b1[3]);
                mma_f16(acc + 16, a1, b0[0], b0[2]);
                mma_f16(acc + 20, a1, b0[1], b0[3]);
                mma_f16(acc + 24, a1, b1[0], b1[2]);
                mma_f16(acc + 28, a1, b1[1], b1[3]);
            }
        }

        // ---- store k-partials (gates overlay dead A region) ----
        __syncthreads();
        float* sg = (float*)(smem + SM_G + kq * 8704);
        {
            const int r = lane >> 2, cc = 2 * (lane & 3);
#pragma unroll
            for (int mi = 0; mi < 2; mi++)
#pragma unroll
                for (int ng = 0; ng < 4; ng++) {
                    const float* a = acc + mi * 16 + ng * 4;
                    int row = mi * 16 + r;
                    int col = nq * 32 + ng * 8 + cc;
                    sg[row * GSTR + col]           = a[0];
                    sg[row * GSTR + col + 1]       = a[1];
                    sg[(row + 8) * GSTR + col]     = a[2];
                    sg[(row + 8) * GSTR + col + 1] = a[3];
                }
        }
        __syncthreads();

        // ---- epilogue: 512 cells, 2 per thread, sum 4 k-partials ----
        {
            const float* sg0 = (const float*)(smem + SM_G);
            const float* sg1 = (const float*)(smem + SM_G + 8704);
            const float* sg2 = (const float*)(smem + SM_G + 17408);
            const float* sg3 = (const float*)(smem + SM_G + 26112);
            const __half2* xph = (const __half2*)(smem + SM_XP);
            __half* Hn = g_Hf[cur ^ 1];
#pragma unroll
            for (int j = 0; j < 2; j++) {
                const int idx = t + j * 256;
                const int b   = idx >> 4;            // 0..31 local batch
                const int gb  = b * GSTR + hl * 4;
                __half2 x01 = xph[b * 32 + hl * 2];
                __half2 x23 = xph[b * 32 + hl * 2 + 1];
                float gi = sg0[gb]   + sg1[gb]   + sg2[gb]   + sg3[gb]   + __low2float(x01)  + bvi;
                float gf = sg0[gb+1] + sg1[gb+1] + sg2[gb+1] + sg3[gb+1] + __high2float(x01) + bvf;
                float go = sg0[gb+2] + sg1[gb+2] + sg2[gb+2] + sg3[gb+2] + __low2float(x23)  + bvo;
                float gc = sg0[gb+3] + sg1[gb+3] + sg2[gb+3] + sg3[gb+3] + __high2float(x23) + bvc;
                float iv = sigmoid_f(gi), fv = sigmoid_f(gf), ov = sigmoid_f(go);
                float cv = tanh_f(gc);
                const int gidx = (bofs + b) * H_ + hglob;
                float cn = fv * g_C[gidx] + iv * cv;
                float hn = ov * tanh_f(cn);
                g_C[gidx] = cn;
                Hn[gidx] = __float2half_rn(hn);
                g_outs[((size_t)s * B_ + bofs + b) * H_ + hglob] = hn;
            }
        }

        // ---- per-group grid barrier (64 CTAs) ----
        __syncthreads();
        if (t == 0) {
            __threadfence();
            atomicAdd(barp, 1u);
            const unsigned tgt = 64u * (unsigned)(s + 1);
            while (*(volatile unsigned*)barp < tgt) { }
            __threadfence();
        }
        __syncthreads();
    }
}

// ---------------- fc + finalize --------------------------------------------
__global__ void fc_kernel(const float* __restrict__ fcW,
                          const float* __restrict__ fcb,
                          float* __restrict__ pred)
{
    int gw = (blockIdx.x * blockDim.x + threadIdx.x) >> 5;
    int lane = threadIdx.x & 31;
    if (gw >= B_ * S_) return;
    int s = gw >> 6;
    int b = gw & 63;
    const float* row = g_outs + ((size_t)s * B_ + b) * H_;
    float sum = 0.0f;
#pragma unroll 4
    for (int h = lane; h < H_; h += 32) sum += row[h] * fcW[h];
#pragma unroll
    for (int o = 16; o; o >>= 1) sum += __shfl_down_sync(0xFFFFFFFFu, sum, o);
    if (lane == 0) pred[(size_t)b * S_ + s] = sum + fcb[0];
}

__global__ void finalize_kernel(float* __restrict__ out, int out_size) {
    int i = blockIdx.x * blockDim.x + threadIdx.x;
    if (i >= B_ * H_) return;
    const int PRED = B_ * S_;
    if (out_size >= PRED + B_ * H_)
        out[PRED + i] = g_outs[((size_t)(S_ - 1) * B_) * H_ + i];
    if (out_size >= PRED + 2 * B_ * H_)
        out[PRED + B_ * H_ + i] = g_C[i];
}

// ---------------------------------------------------------------------------
extern "C" void kernel_launch(void* const* d_in, const int* in_sizes, int n_in,
                              void* d_out, int out_size)
{
    const float* inputs = (const float*)d_in[0];
    const float* H0  = (const float*)d_in[1];
    const float* C0  = (const float*)d_in[2];
    const float* Wxi = (const float*)d_in[3];
    const float* Whi = (const float*)d_in[4];
    const float* bi  = (const float*)d_in[5];
    const float* Wxf = (const float*)d_in[6];
    const float* Whf = (const float*)d_in[7];
    const float* bf  = (const float*)d_in[8];
    const float* Wxo = (const float*)d_in[9];
    const float* Who = (const float*)d_in[10];
    const float* bo  = (const float*)d_in[11];
    const float* Wxc = (const float*)d_in[12];
    const float* Whc = (const float*)d_in[13];
    const float* bc  = (const float*)d_in[14];
    const float* fcW = (const float*)d_in[15];
    const float* fcb = (const float*)d_in[16];
    float* out = (float*)d_out;

    cudaFuncSetAttribute(lstm_persist, cudaFuncAttributeMaxDynamicSharedMemorySize, PSM_TOTAL);
    cudaFuncSetAttribute(xproj_gemm,  cudaFuncAttributeMaxDynamicSharedMemorySize, XP_SMEM);

    conv_x<<<4096, 256>>>(inputs);
    conv_W_t<<<dim3(H_ / 32, 32, 8), dim3(32, 8)>>>(Wxi, Wxf, Wxo, Wxc,
                                                    Whi, Whf, Who, Whc);
    lstm_init<<<(B_ * H_ + 255) / 256, 256>>>(H0, C0);

    xproj_gemm<<<dim3(64, 256), 256, XP_SMEM>>>();

    lstm_persist<<<NCTA, 256, PSM_TOTAL>>>(bi, bf, bo, bc);

    fc_kernel<<<(B_ * S_) / 8, 256>>>(fcW, fcb, out);
    finalize_kernel<<<(B_ * H_ + 255) / 256, 256>>>(out, out_size);
}

// round 17
// speedup vs baseline: 4.2160x; 1.0617x over previous
#include <cuda_runtime.h>
#include <cuda_fp16.h>
#include <math.h>
#include <stdint.h>

#define B_ 64
#define S_ 512
#define D_ 512
#define H_ 1024
#define NCTA 128           // 2 groups x 64 CTAs, all resident (<=148 SMs)

// ---- persist smem map (bytes): W[64 rows] | A[32 rows] | xp ----
#define WS_STR 2064                    // 1024 fp16 + 16B pad
#define SM_A   132096                  // W: 64*2064
#define SM_G   132096                  // gates overlay A (4*8704=34816 <= 66048)
#define SM_XP  198144                  // A ends here
#define PSM_TOTAL 202240               // + xp 32*64*2 = 4096
#define GSTR   68                      // gate row stride (floats, 16B-aligned)

// ---- xproj kernel smem map: ring-4, k64 chunks, tile m128 x n128 ----
#define XQ_A(buf) ((buf)*36864)            // A 128*144 = 18432
#define XQ_B(buf) ((buf)*36864 + 18432)    // B 128*144 = 18432
#define XP_SMEM 147456                     // 4 * 36864

// ---------------- device scratch (allocation-free rule) -------------------
__device__ __half g_x16[(size_t)S_ * B_ * D_];      // [s][b][d] fp16
__device__ __half g_W16[(size_t)4096 * 1536];       // [n=h*4+g][k] fp16 (Wx|Wh)
__device__ __half g_xp16[(size_t)S_ * B_ * 4096];   // x@Wx fp16
__device__ __half g_Hf[2][B_ * H_];                 // H state fp16
__device__ float  g_C[B_ * H_];
__device__ float  g_outs[(size_t)S_ * B_ * H_];     // [s][b][h]
__device__ unsigned g_bars[64];                     // grp 0 at [0], grp 1 at [32]

// ---------------- helpers ---------------------------------------------------
__device__ __forceinline__ uint32_t smem_u32(const void* p) {
    uint32_t a;
    asm("{ .reg .u64 t; cvta.to.shared.u64 t, %1; cvt.u32.u64 %0, t; }" : "=r"(a) : "l"(p));
    return a;
}
__device__ __forceinline__ void ldm4(uint32_t* r, uint32_t addr) {
    asm volatile("ldmatrix.sync.aligned.m8n8.x4.shared.b16 {%0,%1,%2,%3}, [%4];"
                 : "=r"(r[0]), "=r"(r[1]), "=r"(r[2]), "=r"(r[3]) : "r"(addr));
}
__device__ __forceinline__ void mma_f16(float* d, const uint32_t* a, uint32_t b0, uint32_t b1) {
    asm volatile(
        "mma.sync.aligned.m16n8k16.row.col.f32.f16.f16.f32 "
        "{%0,%1,%2,%3}, {%4,%5,%6,%7}, {%8,%9}, {%0,%1,%2,%3};"
        : "+f"(d[0]), "+f"(d[1]), "+f"(d[2]), "+f"(d[3])
        : "r"(a[0]), "r"(a[1]), "r"(a[2]), "r"(a[3]), "r"(b0), "r"(b1));
}
__device__ __forceinline__ void cp16(uint32_t s, const void* g) {
    asm volatile("cp.async.cg.shared.global [%0], [%1], 16;" :: "r"(s), "l"(g));
}
__device__ __forceinline__ float sigmoid_f(float x) {
    return __fdividef(1.0f, 1.0f + __expf(-x));
}
__device__ __forceinline__ float tanh_f(float x) {
    float e = __expf(2.0f * x);
    return __fdividef(e - 1.0f, e + 1.0f);
}

// ---------------- conversion / init kernels --------------------------------
__global__ void conv_x(const float* __restrict__ x) {
    size_t n = (size_t)S_ * B_ * D_;
    for (size_t i = blockIdx.x * (size_t)blockDim.x + threadIdx.x; i < n;
         i += (size_t)gridDim.x * blockDim.x) {
        size_t s = i / (B_ * D_);
        size_t r = i % (B_ * D_);
        size_t b = r / D_, d = r % D_;
        g_x16[i] = __float2half_rn(x[(b * S_ + s) * D_ + d]);
    }
}

// tiled transpose: W[k][h] (fp32) -> g_W16[h*4+g][koff+k] (fp16)
__global__ void conv_W_t(const float* __restrict__ Wxi, const float* __restrict__ Wxf,
                         const float* __restrict__ Wxo, const float* __restrict__ Wxc,
                         const float* __restrict__ Whi, const float* __restrict__ Whf,
                         const float* __restrict__ Who, const float* __restrict__ Whc)
{
    const int z = blockIdx.z;
    const int g = z & 3;
    const bool isWh = z >= 4;
    const int K = isWh ? 1024 : 512;
    const int koff = isWh ? 512 : 0;
    const int k0 = blockIdx.y * 32;
    if (k0 >= K) return;
    const int h0 = blockIdx.x * 32;
    const float* W =
        isWh ? ((g == 0) ? Whi : (g == 1) ? Whf : (g == 2) ? Who : Whc)
             : ((g == 0) ? Wxi : (g == 1) ? Wxf : (g == 2) ? Wxo : Wxc);

    __shared__ __half tile[32][33];
    const int tx = threadIdx.x, ty = threadIdx.y;
#pragma unroll
    for (int j = 0; j < 4; j++) {
        int kk = k0 + ty + j * 8;
        tile[ty + j * 8][tx] = __float2half_rn(W[(size_t)kk * H_ + h0 + tx]);
    }
    __syncthreads();
#pragma unroll
    for (int j = 0; j < 4; j++) {
        int hh = h0 + ty + j * 8;
        g_W16[(size_t)(hh * 4 + g) * 1536 + koff + k0 + tx] = tile[tx][ty + j * 8];
    }
}

__global__ void lstm_init(const float* __restrict__ H0, const float* __restrict__ C0) {
    int i = blockIdx.x * blockDim.x + threadIdx.x;
    if (i < 64) g_bars[i] = 0u;
    if (i < B_ * H_) {
        g_Hf[0][i] = __float2half_rn(H0[i]);
        g_C[i] = C0[i];
    }
}

// ---------------- xproj: m128 x n128 tile, cp.async ring-4 -----------------
__global__ void __launch_bounds__(256) xproj_gemm() {
    extern __shared__ __align__(128) char smem[];
    const uint32_t sb = smem_u32(smem);
    const int t = threadIdx.x, w = t >> 5, lane = t & 31;
    const int m0g = blockIdx.y * 128;
    const int n0g = blockIdx.x * 128;
    const int mw = (w & 3) * 32, nw = (w >> 2) * 64;
    const int frow = (lane & 7) + ((lane & 8) ? 8 : 0);
    const int fk   = (lane & 16) ? 16 : 0;

    auto stage = [&](int kb, int buf) {
#pragma unroll
        for (int i = 0; i < 4; i++) {              // A: 1024 cp16
            int idx = t + i * 256;
            int row = idx >> 3, c = idx & 7;
            cp16(sb + XQ_A(buf) + row * 144 + c * 16,
                 g_x16 + (size_t)(m0g + row) * D_ + kb * 64 + c * 8);
        }
#pragma unroll
        for (int i = 0; i < 4; i++) {              // B: 1024 cp16
            int idx = t + i * 256;
            int row = idx >> 3, c = idx & 7;
            cp16(sb + XQ_B(buf) + row * 144 + c * 16,
                 g_W16 + (size_t)(n0g + row) * 1536 + kb * 64 + c * 8);
        }
        asm volatile("cp.async.commit_group;" ::: "memory");
    };

    float acc[64];
#pragma unroll
    for (int i = 0; i < 64; i++) acc[i] = 0.f;

    stage(0, 0); stage(1, 1); stage(2, 2);

    for (int kb = 0; kb < 8; kb++) {
        const int buf = kb & 3;
        const int rem = 7 - kb;                    // groups that will still complete after kb's
        if (rem >= 2)      asm volatile("cp.async.wait_group 2;" ::: "memory");
        else if (rem == 1) asm volatile("cp.async.wait_group 1;" ::: "memory");
        else               asm volatile("cp.async.wait_group 0;" ::: "memory");
        __syncthreads();

        const uint32_t aB = sb + XQ_A(buf), bB = sb + XQ_B(buf);
#pragma unroll
        for (int ks = 0; ks < 4; ks++) {
            uint32_t fa[2][4], fb[4][4];
#pragma unroll
            for (int mi = 0; mi < 2; mi++)
                ldm4(fa[mi], aB + (mw + mi * 16 + frow) * 144 + fk + ks * 32);
#pragma unroll
            for (int ni = 0; ni < 4; ni++)
                ldm4(fb[ni], bB + (nw + ni * 16 + frow) * 144 + fk + ks * 32);
#pragma unroll
            for (int mi = 0; mi < 2; mi++)
#pragma unroll
                for (int ni = 0; ni < 4; ni++) {
                    float* p = &acc[(mi * 4 + ni) * 8];
                    mma_f16(p,     fa[mi], fb[ni][0], fb[ni][2]);
                    mma_f16(p + 4, fa[mi], fb[ni][1], fb[ni][3]);
                }
        }
        if (kb + 3 < 8) stage(kb + 3, (kb + 3) & 3);   // ring-4: never collides with in-use bufs
    }

#pragma unroll
    for (int mi = 0; mi < 2; mi++)
#pragma unroll
        for (int ni = 0; ni < 4; ni++)
#pragma unroll
            for (int u = 0; u < 2; u++) {
                const float* p = &acc[(mi * 4 + ni) * 8 + u * 4];
                size_t r0 = (size_t)(m0g + mw + mi * 16 + (lane >> 2));
                int    c0 = n0g + nw + ni * 16 + u * 8 + 2 * (lane & 3);
                *(__half2*)(g_xp16 + r0 * 4096 + c0)       = __floats2half2_rn(p[0], p[1]);
                *(__half2*)(g_xp16 + (r0 + 8) * 4096 + c0) = __floats2half2_rn(p[2], p[3]);
            }
}

// ---------------- persistent recurrence: 2 batch groups, C in registers ----
__global__ void __launch_bounds__(256, 1) lstm_persist(
    const float* __restrict__ bi, const float* __restrict__ bf,
    const float* __restrict__ bo, const float* __restrict__ bc)
{
    extern __shared__ __align__(128) char smem[];
    const uint32_t sb = smem_u32(smem);
    const int t    = threadIdx.x;
    const int w    = t >> 5;
    const int lane = t & 31;

    const int bg     = blockIdx.x & 1;          // batch group (0: b 0-31, 1: b 32-63)
    const int nslice = blockIdx.x >> 1;         // 0..63
    const int bofs   = bg * 32;
    const int n0     = nslice * 64;             // gate-row base

    // warp tile: k-quarter x n-half; warp covers m32 n32 k256
    const int kq = w >> 1, nq = w & 1;
    const int frow = (lane & 7) + ((lane & 8) ? 8 : 0);
    const int fk   = (lane & 16) ? 16 : 0;
    const uint32_t aBase = sb + SM_A + (uint32_t)frow * WS_STR + kq * 512 + fk;
    const uint32_t wB0   = sb + (uint32_t)(nq * 32 + frow) * WS_STR      + kq * 512 + fk;
    const uint32_t wB16  = sb + (uint32_t)(nq * 32 + 16 + frow) * WS_STR + kq * 512 + fk;

    // ---- resident Wh fp16: 64 gate rows x 1024 k ----
#pragma unroll
    for (int i = 0; i < 32; i++) {
        int idx = t + i * 256;
        int row = idx >> 7, c16 = idx & 127;
        *(uint4*)(smem + row * WS_STR + c16 * 16) =
            *(const uint4*)(g_W16 + (size_t)(n0 + row) * 1536 + 512 + c16 * 8);
    }

    const int hl    = t & 15;                // invariant under +256
    const int hglob = nslice * 16 + hl;
    const float bvi = bi[hglob], bvf = bf[hglob], bvo = bo[hglob], bvc = bc[hglob];
    unsigned* barp = &g_bars[bg * 32];

    // ---- cell state in registers for the whole sequence ----
    float c_reg[2];
#pragma unroll
    for (int j = 0; j < 2; j++) {
        const int b = (t + j * 256) >> 4;
        c_reg[j] = g_C[(bofs + b) * H_ + hglob];
    }
    __syncthreads();

    for (int s = 0; s < S_; s++) {
        const int cur = s & 1;
        const __half* Hc = g_Hf[cur] + bofs * H_;

        // ---- issue 4 staging chunks; chunk c gives each k-quarter 8 c16 ----
#pragma unroll
        for (int c = 0; c < 4; c++) {
            if (c == 0) {   // xp (fp16, 4 KB) rides in group 0
                cp16(sb + SM_XP + t * 16,
                     g_xp16 + ((size_t)s * B_ + bofs + (t >> 3)) * 4096 + n0 + (t & 7) * 8);
            }
#pragma unroll
            for (int i = 0; i < 4; i++) {
                int idx = t + i * 256;             // 1024 chunks
                int row = idx >> 5, q = idx & 31;
                int c16 = (q >> 3) * 32 + c * 8 + (q & 7);
                cp16(sb + SM_A + row * WS_STR + c16 * 16,
                     Hc + (size_t)row * H_ + c16 * 8);
            }
            asm volatile("cp.async.commit_group;" ::: "memory");
        }

        // ---- MMA: per chunk each warp does 4 ks of its k-quarter -----------
        float acc[32];
#pragma unroll
        for (int i = 0; i < 32; i++) acc[i] = 0.f;

#pragma unroll
        for (int c = 0; c < 4; c++) {
            switch (3 - c) {
                case 3: asm volatile("cp.async.wait_group 3;" ::: "memory"); break;
                case 2: asm volatile("cp.async.wait_group 2;" ::: "memory"); break;
                case 1: asm volatile("cp.async.wait_group 1;" ::: "memory"); break;
                default: asm volatile("cp.async.wait_group 0;" ::: "memory"); break;
            }
            __syncthreads();
#pragma unroll
            for (int ks = 0; ks < 4; ks++) {
                const uint32_t off = c * 128 + ks * 32;
                uint32_t a0[4], a1[4], b0[4], b1[4];
                ldm4(a0, aBase + off);
                ldm4(a1, aBase + 16 * WS_STR + off);
                ldm4(b0, wB0 + off);
                ldm4(b1, wB16 + off);
                mma_f16(acc,      a0, b0[0], b0[2]);
                mma_f16(acc + 4,  a0, b0[1], b0[3]);
                mma_f16(acc + 8,  a0, b1[0], b1[2]);
                mma_f16(acc + 12, a0, b1[1], b1[3]);
                mma_f16(acc + 16, a1, b0[0], b0[2]);
                mma_f16(acc + 20, a1, b0[1], b0[3]);
                mma_f16(acc + 24, a1, b1[0], b1[2]);
                mma_f16(acc + 28, a1, b1[1], b1[3]);
            }
        }

        // ---- store k-partials (gates overlay dead A region) ----
        __syncthreads();
        float* sg = (float*)(smem + SM_G + kq * 8704);
        {
            const int r = lane >> 2, cc = 2 * (lane & 3);
#pragma unroll
            for (int mi = 0; mi < 2; mi++)
#pragma unroll
                for (int ng = 0; ng < 4; ng++) {
                    const float* a = acc + mi * 16 + ng * 4;
                    int row = mi * 16 + r;
                    int col = nq * 32 + ng * 8 + cc;
                    sg[row * GSTR + col]           = a[0];
                    sg[row * GSTR + col + 1]       = a[1];
                    sg[(row + 8) * GSTR + col]     = a[2];
                    sg[(row + 8) * GSTR + col + 1] = a[3];
                }
        }
        __syncthreads();

        // ---- epilogue: 512 cells, 2 per thread, C in registers ----
        {
            const float* sg0 = (const float*)(smem + SM_G);
            const float* sg1 = (const float*)(smem + SM_G + 8704);
            const float* sg2 = (const float*)(smem + SM_G + 17408);
            const float* sg3 = (const float*)(smem + SM_G + 26112);
            const __half2* xph = (const __half2*)(smem + SM_XP);
            __half* Hn = g_Hf[cur ^ 1];
#pragma unroll
            for (int j = 0; j < 2; j++) {
                const int idx = t + j * 256;
                const int b   = idx >> 4;            // 0..31 local batch
                const int gb  = b * GSTR + hl * 4;
                __half2 x01 = xph[b * 32 + hl * 2];
                __half2 x23 = xph[b * 32 + hl * 2 + 1];
                float gi = sg0[gb]   + sg1[gb]   + sg2[gb]   + sg3[gb]   + __low2float(x01)  + bvi;
                float gf = sg0[gb+1] + sg1[gb+1] + sg2[gb+1] + sg3[gb+1] + __high2float(x01) + bvf;
                float go = sg0[gb+2] + sg1[gb+2] + sg2[gb+2] + sg3[gb+2] + __low2float(x23)  + bvo;
                float gc = sg0[gb+3] + sg1[gb+3] + sg2[gb+3] + sg3[gb+3] + __high2float(x23) + bvc;
                float iv = sigmoid_f(gi), fv = sigmoid_f(gf), ov = sigmoid_f(go);
                float cv = tanh_f(gc);
                float cn = fv * c_reg[j] + iv * cv;
                float hn = ov * tanh_f(cn);
                c_reg[j] = cn;
                Hn[(bofs + b) * H_ + hglob] = __float2half_rn(hn);
                g_outs[((size_t)s * B_ + bofs + b) * H_ + hglob] = hn;
            }
        }

        // ---- per-group grid barrier (64 CTAs) ----
        __syncthreads();
        if (t == 0) {
            __threadfence();
            atomicAdd(barp, 1u);
            const unsigned tgt = 64u * (unsigned)(s + 1);
            while (*(volatile unsigned*)barp < tgt) { }
            __threadfence();
        }
        __syncthreads();
    }

    // ---- write back final C ----
#pragma unroll
    for (int j = 0; j < 2; j++) {
        const int b = (t + j * 256) >> 4;
        g_C[(bofs + b) * H_ + hglob] = c_reg[j];
    }
}

// ---------------- fc + finalize --------------------------------------------
__global__ void fc_kernel(const float* __restrict__ fcW,
                          const float* __restrict__ fcb,
                          float* __restrict__ pred)
{
    int gw = (blockIdx.x * blockDim.x + threadIdx.x) >> 5;
    int lane = threadIdx.x & 31;
    if (gw >= B_ * S_) return;
    int s = gw >> 6;
    int b = gw & 63;
    const float* row = g_outs + ((size_t)s * B_ + b) * H_;
    float sum = 0.0f;
#pragma unroll 4
    for (int h = lane; h < H_; h += 32) sum += row[h] * fcW[h];
#pragma unroll
    for (int o = 16; o; o >>= 1) sum += __shfl_down_sync(0xFFFFFFFFu, sum, o);
    if (lane == 0) pred[(size_t)b * S_ + s] = sum + fcb[0];
}

__global__ void finalize_kernel(float* __restrict__ out, int out_size) {
    int i = blockIdx.x * blockDim.x + threadIdx.x;
    if (i >= B_ * H_) return;
    const int PRED = B_ * S_;
    if (out_size >= PRED + B_ * H_)
        out[PRED + i] = g_outs[((size_t)(S_ - 1) * B_) * H_ + i];
    if (out_size >= PRED + 2 * B_ * H_)
        out[PRED + B_ * H_ + i] = g_C[i];
}

// ---------------------------------------------------------------------------
extern "C" void kernel_launch(void* const* d_in, const int* in_sizes, int n_in,
                              void* d_out, int out_size)
{
    const float* inputs = (const float*)d_in[0];
    const float* H0  = (const float*)d_in[1];
    const float* C0  = (const float*)d_in[2];
    const float* Wxi = (const float*)d_in[3];
    const float* Whi = (const float*)d_in[4];
    const float* bi  = (const float*)d_in[5];
    const float* Wxf = (const float*)d_in[6];
    const float* Whf = (const float*)d_in[7];
    const float* bf  = (const float*)d_in[8];
    const float* Wxo = (const float*)d_in[9];
    const float* Who = (const float*)d_in[10];
    const float* bo  = (const float*)d_in[11];
    const float* Wxc = (const float*)d_in[12];
    const float* Whc = (const float*)d_in[13];
    const float* bc  = (const float*)d_in[14];
    const float* fcW = (const float*)d_in[15];
    const float* fcb = (const float*)d_in[16];
    float* out = (float*)d_out;

    cudaFuncSetAttribute(lstm_persist, cudaFuncAttributeMaxDynamicSharedMemorySize, PSM_TOTAL);
    cudaFuncSetAttribute(xproj_gemm,  cudaFuncAttributeMaxDynamicSharedMemorySize, XP_SMEM);

    conv_x<<<4096, 256>>>(inputs);
    conv_W_t<<<dim3(H_ / 32, 32, 8), dim3(32, 8)>>>(Wxi, Wxf, Wxo, Wxc,
                                                    Whi, Whf, Who, Whc);
    lstm_init<<<(B_ * H_ + 255) / 256, 256>>>(H0, C0);

    xproj_gemm<<<dim3(32, 256), 256, XP_SMEM>>>();

    lstm_persist<<<NCTA, 256, PSM_TOTAL>>>(bi, bf, bo, bc);

    fc_kernel<<<(B_ * S_) / 8, 256>>>(fcW, fcb, out);
    finalize_kernel<<<(B_ * H_ + 255) / 256, 256>>>(out, out_size);
}